// round 1
// baseline (speedup 1.0000x reference)
#include <cuda_runtime.h>
#include <cuda_bf16.h>
#include <math.h>

// Problem constants (fixed shapes for this problem instance)
#define BB    4
#define QQ    2048
#define KVN   2048
#define DD    512
#define UQ    60          // int(8 * ln(2048)) = 60 selected queries
#define SPLITS 8          // KV splits for the big masked-max GEMM
#define KV_PER_SPLIT (KVN / SPLITS)   // 256
#define WS_SPLIT 8        // kv splits for weighted-sum kernel
#define KVC   (KVN / WS_SPLIT)        // 256
#define PVS   16          // kv splits for PV GEMM

// ---------------- scratch (static device globals; no dynamic alloc) ----------
__device__ int   g_count[BB * KVN];
__device__ float g_wspart[WS_SPLIT * BB * DD];
__device__ float g_vmpart[WS_SPLIT * BB * DD];
__device__ float g_wsum[BB * DD];
__device__ float g_vmean[BB * DD];
__device__ float g_Mpart[BB * QQ * SPLITS];
__device__ float g_M[BB * QQ];
__device__ int   g_topidx[BB * UQ];
__device__ float g_S1[(size_t)BB * UQ * KVN];           // logits -> probs
__device__ float g_Opart[(size_t)PVS * BB * UQ * DD];   // PV partials

// ---------------- kernel 1: zero counts -------------------------------------
__global__ void zero_count_kernel() {
    int i = blockIdx.x * blockDim.x + threadIdx.x;
    if (i < BB * KVN) g_count[i] = 0;
}

// ---------------- kernel 2: histogram of sample_idx -------------------------
__global__ void count_kernel(const int* __restrict__ sidx, int U) {
    int i = blockIdx.x * blockDim.x + threadIdx.x;
    if (i < BB * U) {
        int b = i / U;
        atomicAdd(&g_count[b * KVN + sidx[i]], 1);
    }
}

// ---------------- kernel 3: weighted key sum + v mean (partials) ------------
// grid (DD/128, WS_SPLIT, BB), block 128
__global__ void wsum_part_kernel(const float* __restrict__ k,
                                 const float* __restrict__ v) {
    int b = blockIdx.z;
    int s = blockIdx.y;
    int d = blockIdx.x * 128 + threadIdx.x;

    __shared__ float cntf[KVC];
    for (int i = threadIdx.x; i < KVC; i += 128)
        cntf[i] = (float)g_count[b * KVN + s * KVC + i];
    __syncthreads();

    const float* kp = k + ((size_t)b * KVN + (size_t)s * KVC) * DD + d;
    const float* vp = v + ((size_t)b * KVN + (size_t)s * KVC) * DD + d;
    float ws = 0.f, vm = 0.f;
#pragma unroll 4
    for (int j = 0; j < KVC; j++) {
        ws += cntf[j] * kp[(size_t)j * DD];
        vm += vp[(size_t)j * DD];
    }
    g_wspart[((size_t)s * BB + b) * DD + d] = ws;
    g_vmpart[((size_t)s * BB + b) * DD + d] = vm;
}

__global__ void wsum_reduce_kernel() {
    int idx = blockIdx.x * blockDim.x + threadIdx.x;
    if (idx >= BB * DD) return;
    int b = idx / DD, d = idx % DD;
    float ws = 0.f, vm = 0.f;
#pragma unroll
    for (int s = 0; s < WS_SPLIT; s++) {
        ws += g_wspart[((size_t)s * BB + b) * DD + d];
        vm += g_vmpart[((size_t)s * BB + b) * DD + d];
    }
    g_wsum[idx] = ws;
    g_vmean[idx] = vm * (1.0f / KVN);
}

// ---------------- kernel 4: masked QK^T row-max (the big one) ---------------
// grid (QQ/128, SPLITS, BB), block 256. Tile 128q x 128kv, d-step 8,
// 8x8 per-thread microtile, running masked max over kv.
__global__ void __launch_bounds__(256, 2)
qkmax_kernel(const float* __restrict__ q, const float* __restrict__ k) {
    int b = blockIdx.z;
    int m0 = blockIdx.x * 128;
    int split = blockIdx.y;
    int kvbase = split * KV_PER_SPLIT;

    const float* qb = q + (size_t)b * QQ * DD;
    const float* kb = k + (size_t)b * KVN * DD;

    __shared__ float qs[8][128];
    __shared__ float ks[8][128];
    __shared__ int   cmask[128];
    __shared__ float red[128][17];

    int tid = threadIdx.x;
    int tx = tid & 15, ty = tid >> 4;
    int r = tid >> 1, h = (tid & 1) * 4;

    float rowmax[8];
#pragma unroll
    for (int i = 0; i < 8; i++) rowmax[i] = -3.0e38f;

    for (int kvt = 0; kvt < KV_PER_SPLIT / 128; kvt++) {
        int n0 = kvbase + kvt * 128;
        __syncthreads();                 // protect cmask from prior readers
        if (tid < 128) cmask[tid] = g_count[b * KVN + n0 + tid];

        float acc[8][8];
#pragma unroll
        for (int i = 0; i < 8; i++)
#pragma unroll
            for (int j = 0; j < 8; j++) acc[i][j] = 0.f;

        for (int dt = 0; dt < DD; dt += 8) {
            __syncthreads();
            float4 v4 = *(const float4*)(qb + (size_t)(m0 + r) * DD + dt + h);
            qs[h + 0][r] = v4.x; qs[h + 1][r] = v4.y;
            qs[h + 2][r] = v4.z; qs[h + 3][r] = v4.w;
            float4 w4 = *(const float4*)(kb + (size_t)(n0 + r) * DD + dt + h);
            ks[h + 0][r] = w4.x; ks[h + 1][r] = w4.y;
            ks[h + 2][r] = w4.z; ks[h + 3][r] = w4.w;
            __syncthreads();
#pragma unroll
            for (int kk = 0; kk < 8; kk++) {
                float a[8], bb[8];
                *(float4*)&a[0]  = *(float4*)&qs[kk][ty * 8];
                *(float4*)&a[4]  = *(float4*)&qs[kk][ty * 8 + 4];
                *(float4*)&bb[0] = *(float4*)&ks[kk][tx * 8];
                *(float4*)&bb[4] = *(float4*)&ks[kk][tx * 8 + 4];
#pragma unroll
                for (int i = 0; i < 8; i++)
#pragma unroll
                    for (int j = 0; j < 8; j++)
                        acc[i][j] += a[i] * bb[j];
            }
        }
        __syncthreads();
#pragma unroll
        for (int j = 0; j < 8; j++) {
            if (cmask[tx * 8 + j] > 0) {
#pragma unroll
                for (int i = 0; i < 8; i++)
                    rowmax[i] = fmaxf(rowmax[i], acc[i][j]);
            }
        }
    }

    // reduce rowmax across the 16 tx threads that share each row
#pragma unroll
    for (int i = 0; i < 8; i++) red[ty * 8 + i][tx] = rowmax[i];
    __syncthreads();
    if (tid < 128) {
        float m = red[tid][0];
#pragma unroll
        for (int x = 1; x < 16; x++) m = fmaxf(m, red[tid][x]);
        g_Mpart[((size_t)b * QQ + m0 + tid) * SPLITS + split] = m;
    }
}

// ---------------- kernel 5: finalize M = max - dot(q,wsum)/U ----------------
// block 256 = 8 warps, one q per warp
__global__ void finalize_kernel(const float* __restrict__ q, float Uf) {
    int gq = blockIdx.x * 8 + (threadIdx.x >> 5);
    int lane = threadIdx.x & 31;
    if (gq >= BB * QQ) return;
    int b = gq / QQ;
    const float* qr = q + (size_t)gq * DD;
    const float* ws = g_wsum + b * DD;
    float s = 0.f;
#pragma unroll
    for (int t = 0; t < DD / 128; t++) {
        int d = t * 128 + lane * 4;
        float4 a = *(const float4*)(qr + d);
        float4 w = *(const float4*)(ws + d);
        s += a.x * w.x + a.y * w.y + a.z * w.z + a.w * w.w;
    }
#pragma unroll
    for (int off = 16; off > 0; off >>= 1)
        s += __shfl_xor_sync(0xffffffffu, s, off);
    if (lane == 0) {
        float m = -3.0e38f;
#pragma unroll
        for (int sp = 0; sp < SPLITS; sp++)
            m = fmaxf(m, g_Mpart[(size_t)gq * SPLITS + sp]);
        g_M[gq] = m - s / Uf;
    }
}

// ---------------- kernel 6: top-60 per batch (value desc, index asc ties) ---
__global__ void topk_kernel() {
    int b = blockIdx.x;
    __shared__ float vals[QQ];
    __shared__ float rv[256];
    __shared__ int   ri[256];
    int tid = threadIdx.x;
    for (int i = tid; i < QQ; i += 256) vals[i] = g_M[b * QQ + i];
    __syncthreads();
    for (int it = 0; it < UQ; it++) {
        float bv = -3.4e38f; int bi = QQ;
        for (int i = tid; i < QQ; i += 256) {
            float vv = vals[i];
            if (vv > bv || (vv == bv && i < bi)) { bv = vv; bi = i; }
        }
        rv[tid] = bv; ri[tid] = bi;
        __syncthreads();
        for (int s = 128; s > 0; s >>= 1) {
            if (tid < s) {
                float ov = rv[tid + s]; int oi = ri[tid + s];
                if (ov > rv[tid] || (ov == rv[tid] && oi < ri[tid])) {
                    rv[tid] = ov; ri[tid] = oi;
                }
            }
            __syncthreads();
        }
        if (tid == 0) {
            g_topidx[b * UQ + it] = ri[0];
            vals[ri[0]] = -3.4e38f;
        }
        __syncthreads();
    }
}

// ---------------- kernel 7: fill output with v-mean -------------------------
__global__ void fill_kernel(float* __restrict__ out) {
    size_t f = (size_t)blockIdx.x * 256 + threadIdx.x;   // float4 index
    int d4 = (int)(f & (DD / 4 - 1));
    size_t row = f >> 7;          // / (DD/4)
    int b = (int)(row >> 11);     // / QQ
    float4 val = *(const float4*)(g_vmean + b * DD + d4 * 4);
    ((float4*)out)[f] = val;
}

// ---------------- kernel 8: logits S1 = q_bar @ k^T * scale -----------------
// grid (KVN/128, BB), block 256; thread microtile 4i x 8kv, d-step 16
__global__ void __launch_bounds__(256)
logits_kernel(const float* __restrict__ q, const float* __restrict__ k) {
    int b = blockIdx.y;
    int n0 = blockIdx.x * 128;
    __shared__ int   tix[UQ];
    __shared__ float qs2[16][64];
    __shared__ float ks2[16][128];
    int tid = threadIdx.x;
    if (tid < UQ) tix[tid] = g_topidx[b * UQ + tid];

    int tx = tid & 15, ty = tid >> 4;
    float acc[4][8];
#pragma unroll
    for (int i = 0; i < 4; i++)
#pragma unroll
        for (int j = 0; j < 8; j++) acc[i][j] = 0.f;

    const float* qb = q + (size_t)b * QQ * DD;
    const float* kb = k + (size_t)b * KVN * DD;

    for (int dt = 0; dt < DD; dt += 16) {
        __syncthreads();
        if (tid < 240) {
            int i = tid >> 2, hh = (tid & 3) * 4;
            float4 v4 = *(const float4*)(qb + (size_t)tix[i] * DD + dt + hh);
            qs2[hh + 0][i] = v4.x; qs2[hh + 1][i] = v4.y;
            qs2[hh + 2][i] = v4.z; qs2[hh + 3][i] = v4.w;
        }
        {
            int r2 = tid >> 1, h2 = (tid & 1) * 8;
            float4 a4 = *(const float4*)(kb + (size_t)(n0 + r2) * DD + dt + h2);
            float4 b4 = *(const float4*)(kb + (size_t)(n0 + r2) * DD + dt + h2 + 4);
            ks2[h2 + 0][r2] = a4.x; ks2[h2 + 1][r2] = a4.y;
            ks2[h2 + 2][r2] = a4.z; ks2[h2 + 3][r2] = a4.w;
            ks2[h2 + 4][r2] = b4.x; ks2[h2 + 5][r2] = b4.y;
            ks2[h2 + 6][r2] = b4.z; ks2[h2 + 7][r2] = b4.w;
        }
        __syncthreads();
#pragma unroll
        for (int kk = 0; kk < 16; kk++) {
            float a[4], bb[8];
            *(float4*)&a[0]  = *(float4*)&qs2[kk][ty * 4];
            *(float4*)&bb[0] = *(float4*)&ks2[kk][tx * 8];
            *(float4*)&bb[4] = *(float4*)&ks2[kk][tx * 8 + 4];
#pragma unroll
            for (int i = 0; i < 4; i++)
#pragma unroll
                for (int j = 0; j < 8; j++)
                    acc[i][j] += a[i] * bb[j];
        }
    }
    float scale = rsqrtf((float)KVN);
#pragma unroll
    for (int ii = 0; ii < 4; ii++) {
        int i = ty * 4 + ii;
        if (i < UQ) {
#pragma unroll
            for (int j = 0; j < 8; j++)
                g_S1[((size_t)b * UQ + i) * KVN + n0 + tx * 8 + j] =
                    acc[ii][j] * scale;
        }
    }
}

// ---------------- kernel 9: row softmax over S1 ------------------------------
__global__ void softmax_kernel() {
    int row = blockIdx.x;   // b*UQ + i
    float* p = g_S1 + (size_t)row * KVN;
    __shared__ float sred[256];
    int tid = threadIdx.x;

    float m = -3.4e38f;
    for (int i = tid; i < KVN; i += 256) m = fmaxf(m, p[i]);
    sred[tid] = m; __syncthreads();
    for (int s = 128; s > 0; s >>= 1) {
        if (tid < s) sred[tid] = fmaxf(sred[tid], sred[tid + s]);
        __syncthreads();
    }
    m = sred[0];
    __syncthreads();

    float sum = 0.f;
    for (int i = tid; i < KVN; i += 256) {
        float e = expf(p[i] - m);
        p[i] = e;
        sum += e;
    }
    sred[tid] = sum; __syncthreads();
    for (int s = 128; s > 0; s >>= 1) {
        if (tid < s) sred[tid] += sred[tid + s];
        __syncthreads();
    }
    float inv = 1.0f / sred[0];
    for (int i = tid; i < KVN; i += 256) p[i] *= inv;
}

// ---------------- kernel 10: O partials = P @ V (split kv) ------------------
// grid (DD/128, PVS, BB), block 256; microtile 4i x 8d, kv-step 16
__global__ void __launch_bounds__(256)
pv_kernel(const float* __restrict__ v) {
    int b = blockIdx.z;
    int s = blockIdx.y;
    int d0 = blockIdx.x * 128;
    int kv0 = s * (KVN / PVS);     // 128

    __shared__ float ps[16][64];
    __shared__ float vs[16][128];
    int tid = threadIdx.x;
    int tx = tid & 15, ty = tid >> 4;
    float acc[4][8];
#pragma unroll
    for (int i = 0; i < 4; i++)
#pragma unroll
        for (int j = 0; j < 8; j++) acc[i][j] = 0.f;

    const float* vb = v + (size_t)b * KVN * DD;

    for (int kt = 0; kt < KVN / PVS; kt += 16) {
        __syncthreads();
        if (tid < 240) {
            int i = tid >> 2, hh = (tid & 3) * 4;
            float4 a4 = *(const float4*)(g_S1 + ((size_t)b * UQ + i) * KVN
                                         + kv0 + kt + hh);
            ps[hh + 0][i] = a4.x; ps[hh + 1][i] = a4.y;
            ps[hh + 2][i] = a4.z; ps[hh + 3][i] = a4.w;
        }
        {
            int kkr = tid >> 4, dc = (tid & 15) * 8;
            float4 a4 = *(const float4*)(vb + (size_t)(kv0 + kt + kkr) * DD + d0 + dc);
            float4 b4 = *(const float4*)(vb + (size_t)(kv0 + kt + kkr) * DD + d0 + dc + 4);
            vs[kkr][dc + 0] = a4.x; vs[kkr][dc + 1] = a4.y;
            vs[kkr][dc + 2] = a4.z; vs[kkr][dc + 3] = a4.w;
            vs[kkr][dc + 4] = b4.x; vs[kkr][dc + 5] = b4.y;
            vs[kkr][dc + 6] = b4.z; vs[kkr][dc + 7] = b4.w;
        }
        __syncthreads();
#pragma unroll
        for (int kk = 0; kk < 16; kk++) {
            float a[4], bb[8];
            *(float4*)&a[0]  = *(float4*)&ps[kk][ty * 4];
            *(float4*)&bb[0] = *(float4*)&vs[kk][tx * 8];
            *(float4*)&bb[4] = *(float4*)&vs[kk][tx * 8 + 4];
#pragma unroll
            for (int i = 0; i < 4; i++)
#pragma unroll
                for (int j = 0; j < 8; j++)
                    acc[i][j] += a[i] * bb[j];
        }
    }
#pragma unroll
    for (int ii = 0; ii < 4; ii++) {
        int i = ty * 4 + ii;
        if (i < UQ) {
#pragma unroll
            for (int j = 0; j < 8; j++)
                g_Opart[(((size_t)s * BB + b) * UQ + i) * DD + d0 + tx * 8 + j] =
                    acc[ii][j];
        }
    }
}

// ---------------- kernel 11: reduce PV partials + scatter to output ---------
__global__ void oreduce_kernel(float* __restrict__ out) {
    int idx = blockIdx.x * 256 + threadIdx.x;   // over BB*UQ*DD
    if (idx >= BB * UQ * DD) return;
    int d = idx % DD;
    int rest = idx / DD;
    int i = rest % UQ;
    int b = rest / UQ;
    float s = 0.f;
#pragma unroll
    for (int p = 0; p < PVS; p++)
        s += g_Opart[(((size_t)p * BB + b) * UQ + i) * DD + d];
    int row = g_topidx[b * UQ + i];
    out[((size_t)b * QQ + row) * DD + d] = s;
}

// ---------------- launch ------------------------------------------------------
extern "C" void kernel_launch(void* const* d_in, const int* in_sizes, int n_in,
                              void* d_out, int out_size) {
    const float* q    = (const float*)d_in[0];
    const float* k    = (const float*)d_in[1];
    const float* v    = (const float*)d_in[2];
    const int*   sidx = (const int*)d_in[3];
    float* out = (float*)d_out;
    int U = in_sizes[3] / BB;   // 15615

    zero_count_kernel<<<(BB * KVN + 255) / 256, 256>>>();
    count_kernel<<<(BB * U + 255) / 256, 256>>>(sidx, U);
    wsum_part_kernel<<<dim3(DD / 128, WS_SPLIT, BB), 128>>>(k, v);
    wsum_reduce_kernel<<<(BB * DD + 255) / 256, 256>>>();
    qkmax_kernel<<<dim3(QQ / 128, SPLITS, BB), 256>>>(q, k);
    finalize_kernel<<<(BB * QQ) / 8, 256>>>(q, (float)U);
    topk_kernel<<<BB, 256>>>();
    fill_kernel<<<(BB * QQ * DD / 4) / 256, 256>>>(out);
    logits_kernel<<<dim3(KVN / 128, BB), 256>>>(q, k);
    softmax_kernel<<<BB * UQ, 256>>>();
    pv_kernel<<<dim3(DD / 128, PVS, BB), 256>>>(v);
    oreduce_kernel<<<(BB * UQ * DD + 255) / 256, 256>>>(out);
}

// round 2
// speedup vs baseline: 1.5052x; 1.5052x over previous
#include <cuda_runtime.h>
#include <cuda_bf16.h>
#include <math.h>
#include <stdint.h>

// Problem constants
#define BB    4
#define QQ    2048
#define KVN   2048
#define DD    512
#define UQ    60
#define NTILES (KVN / 128)       // 16 kv tiles for qkmax partial max
#define WS_SPLIT 8
#define KVC   (KVN / WS_SPLIT)   // 256
#define PVS   16

// ---------------- scratch ----------------------------------------------------
__device__ int   g_count[BB * KVN];
__device__ float g_wspart[WS_SPLIT * BB * DD];
__device__ float g_vmpart[WS_SPLIT * BB * DD];
__device__ float g_wsum[BB * DD];
__device__ float g_vmean[BB * DD];
__device__ float g_Mpart[BB * QQ * NTILES];
__device__ float g_M[BB * QQ];
__device__ int   g_topidx[BB * UQ];
__device__ float g_S1[(size_t)BB * UQ * KVN];
__device__ float g_Opart[(size_t)PVS * BB * UQ * DD];
__device__ __nv_bfloat16 g_qhi[(size_t)BB * QQ * DD];
__device__ __nv_bfloat16 g_qlo[(size_t)BB * QQ * DD];
__device__ __nv_bfloat16 g_khi[(size_t)BB * KVN * DD];
__device__ __nv_bfloat16 g_klo[(size_t)BB * KVN * DD];

// ---------------- PTX helpers -------------------------------------------------
__device__ __forceinline__ uint32_t smem_u32(const void* p) {
    return (uint32_t)__cvta_generic_to_shared(p);
}
__device__ __forceinline__ void cpa16(uint32_t saddr, const void* g) {
    asm volatile("cp.async.cg.shared.global [%0], [%1], 16;" :: "r"(saddr), "l"(g));
}
__device__ __forceinline__ void ldsm4(uint32_t& r0, uint32_t& r1, uint32_t& r2,
                                      uint32_t& r3, uint32_t addr) {
    asm volatile("ldmatrix.sync.aligned.m8n8.x4.shared.b16 {%0,%1,%2,%3}, [%4];"
                 : "=r"(r0), "=r"(r1), "=r"(r2), "=r"(r3) : "r"(addr));
}
__device__ __forceinline__ void mma16816(float* c, const uint32_t* a,
                                         uint32_t b0, uint32_t b1) {
    asm volatile(
        "mma.sync.aligned.m16n8k16.row.col.f32.bf16.bf16.f32 "
        "{%0,%1,%2,%3}, {%4,%5,%6,%7}, {%8,%9}, {%0,%1,%2,%3};"
        : "+f"(c[0]), "+f"(c[1]), "+f"(c[2]), "+f"(c[3])
        : "r"(a[0]), "r"(a[1]), "r"(a[2]), "r"(a[3]), "r"(b0), "r"(b1));
}

// ---------------- kernel 0: bf16 hi/lo split of q and k -----------------------
__global__ void split_kernel(const float* __restrict__ q, const float* __restrict__ k) {
    size_t i = (size_t)blockIdx.x * 256 + threadIdx.x;   // float4 index
    float4 a = ((const float4*)q)[i];
    __nv_bfloat162 h01, h23, l01, l23;
    h01.x = __float2bfloat16(a.x); h01.y = __float2bfloat16(a.y);
    h23.x = __float2bfloat16(a.z); h23.y = __float2bfloat16(a.w);
    l01.x = __float2bfloat16(a.x - __bfloat162float(h01.x));
    l01.y = __float2bfloat16(a.y - __bfloat162float(h01.y));
    l23.x = __float2bfloat16(a.z - __bfloat162float(h23.x));
    l23.y = __float2bfloat16(a.w - __bfloat162float(h23.y));
    ((__nv_bfloat162*)g_qhi)[i * 2] = h01; ((__nv_bfloat162*)g_qhi)[i * 2 + 1] = h23;
    ((__nv_bfloat162*)g_qlo)[i * 2] = l01; ((__nv_bfloat162*)g_qlo)[i * 2 + 1] = l23;

    float4 bvec = ((const float4*)k)[i];
    h01.x = __float2bfloat16(bvec.x); h01.y = __float2bfloat16(bvec.y);
    h23.x = __float2bfloat16(bvec.z); h23.y = __float2bfloat16(bvec.w);
    l01.x = __float2bfloat16(bvec.x - __bfloat162float(h01.x));
    l01.y = __float2bfloat16(bvec.y - __bfloat162float(h01.y));
    l23.x = __float2bfloat16(bvec.z - __bfloat162float(h23.x));
    l23.y = __float2bfloat16(bvec.w - __bfloat162float(h23.y));
    ((__nv_bfloat162*)g_khi)[i * 2] = h01; ((__nv_bfloat162*)g_khi)[i * 2 + 1] = h23;
    ((__nv_bfloat162*)g_klo)[i * 2] = l01; ((__nv_bfloat162*)g_klo)[i * 2 + 1] = l23;
}

// ---------------- kernel 1: zero counts ---------------------------------------
__global__ void zero_count_kernel() {
    int i = blockIdx.x * blockDim.x + threadIdx.x;
    if (i < BB * KVN) g_count[i] = 0;
}

// ---------------- kernel 2: histogram of sample_idx ---------------------------
__global__ void count_kernel(const int* __restrict__ sidx, int U) {
    int i = blockIdx.x * blockDim.x + threadIdx.x;
    if (i < BB * U) {
        int b = i / U;
        atomicAdd(&g_count[b * KVN + sidx[i]], 1);
    }
}

// ---------------- kernel 3: weighted key sum + v mean -------------------------
__global__ void wsum_part_kernel(const float* __restrict__ k,
                                 const float* __restrict__ v) {
    int b = blockIdx.z;
    int s = blockIdx.y;
    int d = blockIdx.x * 128 + threadIdx.x;

    __shared__ float cntf[KVC];
    for (int i = threadIdx.x; i < KVC; i += 128)
        cntf[i] = (float)g_count[b * KVN + s * KVC + i];
    __syncthreads();

    const float* kp = k + ((size_t)b * KVN + (size_t)s * KVC) * DD + d;
    const float* vp = v + ((size_t)b * KVN + (size_t)s * KVC) * DD + d;
    float ws = 0.f, vm = 0.f;
#pragma unroll 4
    for (int j = 0; j < KVC; j++) {
        ws += cntf[j] * kp[(size_t)j * DD];
        vm += vp[(size_t)j * DD];
    }
    g_wspart[((size_t)s * BB + b) * DD + d] = ws;
    g_vmpart[((size_t)s * BB + b) * DD + d] = vm;
}

__global__ void wsum_reduce_kernel() {
    int idx = blockIdx.x * blockDim.x + threadIdx.x;
    if (idx >= BB * DD) return;
    int b = idx / DD, d = idx % DD;
    float ws = 0.f, vm = 0.f;
#pragma unroll
    for (int s = 0; s < WS_SPLIT; s++) {
        ws += g_wspart[((size_t)s * BB + b) * DD + d];
        vm += g_vmpart[((size_t)s * BB + b) * DD + d];
    }
    g_wsum[idx] = ws;
    g_vmean[idx] = vm * (1.0f / KVN);
}

// ---------------- kernel 4: masked QK^T row-max (tensor cores) ----------------
// grid (QQ/128, KVN/128, BB), block 256 (8 warps: 2m x 4n), warp tile 64x32.
// S = qhi*khi + qhi*klo + qlo*khi (fp32 HMMA accum), masked row-max.
__global__ void __launch_bounds__(256, 1)
qkmax_tc_kernel() {
    __shared__ __nv_bfloat16 sA[2][128][40];   // [buf][row][ hi:0-15 | lo:16-31 ] pad 40
    __shared__ __nv_bfloat16 sB[2][128][40];
    __shared__ int   cmask[128];
    __shared__ float smax[128][4];

    const int tid = threadIdx.x, lane = tid & 31, warp = tid >> 5;
    const int wm = warp >> 2, wn = warp & 3;
    const int b = blockIdx.z;
    const int m0 = blockIdx.x * 128, n0 = blockIdx.y * 128;

    const __nv_bfloat16* qh = g_qhi + (size_t)b * QQ * DD;
    const __nv_bfloat16* ql = g_qlo + (size_t)b * QQ * DD;
    const __nv_bfloat16* kh = g_khi + (size_t)b * KVN * DD;
    const __nv_bfloat16* kl = g_klo + (size_t)b * KVN * DD;

    if (tid < 128) cmask[tid] = g_count[b * KVN + n0 + tid];

    // cp.async staging addresses
    const int lrow = tid >> 1, lhalf = tid & 1;
    const size_t gaoff = (size_t)(m0 + lrow) * DD + lhalf * 8;
    const size_t gboff = (size_t)(n0 + lrow) * DD + lhalf * 8;
    const uint32_t saA = smem_u32(&sA[0][lrow][lhalf * 8]);
    const uint32_t saB = smem_u32(&sB[0][lrow][lhalf * 8]);
    const uint32_t BUFSTRIDE = 128 * 40 * 2;   // 10240 bytes

    // ldmatrix base addresses
    const int lr = lane & 15;
    const int lc8 = (lane >> 4) * 8;
    const uint32_t aAh = smem_u32(&sA[0][wm * 64 + lr][lc8]);
    const uint32_t aBh = smem_u32(&sB[0][wn * 32 + lr][lc8]);

    float acc[4][4][4];
#pragma unroll
    for (int mt = 0; mt < 4; mt++)
#pragma unroll
        for (int nt = 0; nt < 4; nt++)
#pragma unroll
            for (int r = 0; r < 4; r++) acc[mt][nt][r] = 0.f;

    // issue k-step ks into buffer ks&1
    auto issue = [&](int ks) {
        uint32_t bo = (uint32_t)(ks & 1) * BUFSTRIDE;
        int dt = ks * 16;
        cpa16(saA + bo,      qh + gaoff + dt);
        cpa16(saA + bo + 32, ql + gaoff + dt);
        cpa16(saB + bo,      kh + gboff + dt);
        cpa16(saB + bo + 32, kl + gboff + dt);
        asm volatile("cp.async.commit_group;");
    };

    issue(0);
#pragma unroll 1
    for (int ks = 0; ks < 32; ks++) {
        if (ks < 31) {
            issue(ks + 1);
            asm volatile("cp.async.wait_group 1;");
        } else {
            asm volatile("cp.async.wait_group 0;");
        }
        __syncthreads();

        uint32_t bo = (uint32_t)(ks & 1) * BUFSTRIDE;
        uint32_t ah[4][4], al[4][4], bh[2][4], bl[2][4];
#pragma unroll
        for (int mt = 0; mt < 4; mt++) {
            ldsm4(ah[mt][0], ah[mt][1], ah[mt][2], ah[mt][3], aAh + bo + mt * 1280);
            ldsm4(al[mt][0], al[mt][1], al[mt][2], al[mt][3], aAh + bo + mt * 1280 + 32);
        }
#pragma unroll
        for (int nc = 0; nc < 2; nc++) {
            ldsm4(bh[nc][0], bh[nc][1], bh[nc][2], bh[nc][3], aBh + bo + nc * 1280);
            ldsm4(bl[nc][0], bl[nc][1], bl[nc][2], bl[nc][3], aBh + bo + nc * 1280 + 32);
        }
#pragma unroll
        for (int mt = 0; mt < 4; mt++) {
#pragma unroll
            for (int nt = 0; nt < 4; nt++) {
                int nc = nt >> 1, s = nt & 1;
                mma16816(acc[mt][nt], ah[mt], bh[nc][s], bh[nc][2 + s]);
                mma16816(acc[mt][nt], ah[mt], bl[nc][s], bl[nc][2 + s]);
                mma16816(acc[mt][nt], al[mt], bh[nc][s], bh[nc][2 + s]);
            }
        }
        __syncthreads();
    }

    // ---- masked row-max epilogue ----
    float rm[8];
#pragma unroll
    for (int i = 0; i < 8; i++) rm[i] = -3.0e38f;
#pragma unroll
    for (int nt = 0; nt < 4; nt++) {
        int c0 = wn * 32 + nt * 8 + (lane & 3) * 2;
        bool m0ok = cmask[c0] > 0;
        bool m1ok = cmask[c0 + 1] > 0;
#pragma unroll
        for (int mt = 0; mt < 4; mt++) {
            if (m0ok) {
                rm[mt * 2]     = fmaxf(rm[mt * 2],     acc[mt][nt][0]);
                rm[mt * 2 + 1] = fmaxf(rm[mt * 2 + 1], acc[mt][nt][2]);
            }
            if (m1ok) {
                rm[mt * 2]     = fmaxf(rm[mt * 2],     acc[mt][nt][1]);
                rm[mt * 2 + 1] = fmaxf(rm[mt * 2 + 1], acc[mt][nt][3]);
            }
        }
    }
#pragma unroll
    for (int i = 0; i < 8; i++) {
        rm[i] = fmaxf(rm[i], __shfl_xor_sync(0xffffffffu, rm[i], 1));
        rm[i] = fmaxf(rm[i], __shfl_xor_sync(0xffffffffu, rm[i], 2));
    }
    if ((lane & 3) == 0) {
        int g = lane >> 2;
#pragma unroll
        for (int mt = 0; mt < 4; mt++) {
            smax[wm * 64 + mt * 16 + g][wn]     = rm[mt * 2];
            smax[wm * 64 + mt * 16 + g + 8][wn] = rm[mt * 2 + 1];
        }
    }
    __syncthreads();
    if (tid < 128) {
        float m = fmaxf(fmaxf(smax[tid][0], smax[tid][1]),
                        fmaxf(smax[tid][2], smax[tid][3]));
        g_Mpart[((size_t)b * QQ + m0 + tid) * NTILES + blockIdx.y] = m;
    }
}

// ---------------- kernel 5: finalize M = max - dot(q,wsum)/U ------------------
__global__ void finalize_kernel(const float* __restrict__ q, float Uf) {
    int gq = blockIdx.x * 8 + (threadIdx.x >> 5);
    int lane = threadIdx.x & 31;
    if (gq >= BB * QQ) return;
    int b = gq / QQ;
    const float* qr = q + (size_t)gq * DD;
    const float* ws = g_wsum + b * DD;
    float s = 0.f;
#pragma unroll
    for (int t = 0; t < DD / 128; t++) {
        int d = t * 128 + lane * 4;
        float4 a = *(const float4*)(qr + d);
        float4 w = *(const float4*)(ws + d);
        s += a.x * w.x + a.y * w.y + a.z * w.z + a.w * w.w;
    }
#pragma unroll
    for (int off = 16; off > 0; off >>= 1)
        s += __shfl_xor_sync(0xffffffffu, s, off);
    if (lane == 0) {
        float m = -3.0e38f;
#pragma unroll
        for (int sp = 0; sp < NTILES; sp++)
            m = fmaxf(m, g_Mpart[(size_t)gq * NTILES + sp]);
        g_M[gq] = m - s / Uf;
    }
}

// ---------------- kernel 6: top-60 per batch -----------------------------------
__global__ void topk_kernel() {
    int b = blockIdx.x;
    __shared__ float vals[QQ];
    __shared__ float rv[256];
    __shared__ int   ri[256];
    int tid = threadIdx.x;
    for (int i = tid; i < QQ; i += 256) vals[i] = g_M[b * QQ + i];
    __syncthreads();
    for (int it = 0; it < UQ; it++) {
        float bv = -3.4e38f; int bi = QQ;
        for (int i = tid; i < QQ; i += 256) {
            float vv = vals[i];
            if (vv > bv || (vv == bv && i < bi)) { bv = vv; bi = i; }
        }
        rv[tid] = bv; ri[tid] = bi;
        __syncthreads();
        for (int s = 128; s > 0; s >>= 1) {
            if (tid < s) {
                float ov = rv[tid + s]; int oi = ri[tid + s];
                if (ov > rv[tid] || (ov == rv[tid] && oi < ri[tid])) {
                    rv[tid] = ov; ri[tid] = oi;
                }
            }
            __syncthreads();
        }
        if (tid == 0) {
            g_topidx[b * UQ + it] = ri[0];
            vals[ri[0]] = -3.4e38f;
        }
        __syncthreads();
    }
}

// ---------------- kernel 7: fill output with v-mean ----------------------------
__global__ void fill_kernel(float* __restrict__ out) {
    size_t f = (size_t)blockIdx.x * 256 + threadIdx.x;
    int d4 = (int)(f & (DD / 4 - 1));
    size_t row = f >> 7;
    int b = (int)(row >> 11);
    float4 val = *(const float4*)(g_vmean + b * DD + d4 * 4);
    ((float4*)out)[f] = val;
}

// ---------------- kernel 8: logits S1 = q_bar @ k^T * scale --------------------
__global__ void __launch_bounds__(256)
logits_kernel(const float* __restrict__ q, const float* __restrict__ k) {
    int b = blockIdx.y;
    int n0 = blockIdx.x * 128;
    __shared__ int   tix[UQ];
    __shared__ float qs2[16][64];
    __shared__ float ks2[16][128];
    int tid = threadIdx.x;
    if (tid < UQ) tix[tid] = g_topidx[b * UQ + tid];

    int tx = tid & 15, ty = tid >> 4;
    float acc[4][8];
#pragma unroll
    for (int i = 0; i < 4; i++)
#pragma unroll
        for (int j = 0; j < 8; j++) acc[i][j] = 0.f;

    const float* qb = q + (size_t)b * QQ * DD;
    const float* kb = k + (size_t)b * KVN * DD;

    for (int dt = 0; dt < DD; dt += 16) {
        __syncthreads();
        if (tid < 240) {
            int i = tid >> 2, hh = (tid & 3) * 4;
            float4 v4 = *(const float4*)(qb + (size_t)tix[i] * DD + dt + hh);
            qs2[hh + 0][i] = v4.x; qs2[hh + 1][i] = v4.y;
            qs2[hh + 2][i] = v4.z; qs2[hh + 3][i] = v4.w;
        }
        {
            int r2 = tid >> 1, h2 = (tid & 1) * 8;
            float4 a4 = *(const float4*)(kb + (size_t)(n0 + r2) * DD + dt + h2);
            float4 b4 = *(const float4*)(kb + (size_t)(n0 + r2) * DD + dt + h2 + 4);
            ks2[h2 + 0][r2] = a4.x; ks2[h2 + 1][r2] = a4.y;
            ks2[h2 + 2][r2] = a4.z; ks2[h2 + 3][r2] = a4.w;
            ks2[h2 + 4][r2] = b4.x; ks2[h2 + 5][r2] = b4.y;
            ks2[h2 + 6][r2] = b4.z; ks2[h2 + 7][r2] = b4.w;
        }
        __syncthreads();
#pragma unroll
        for (int kk = 0; kk < 16; kk++) {
            float a[4], bb[8];
            *(float4*)&a[0]  = *(float4*)&qs2[kk][ty * 4];
            *(float4*)&bb[0] = *(float4*)&ks2[kk][tx * 8];
            *(float4*)&bb[4] = *(float4*)&ks2[kk][tx * 8 + 4];
#pragma unroll
            for (int i = 0; i < 4; i++)
#pragma unroll
                for (int j = 0; j < 8; j++)
                    acc[i][j] += a[i] * bb[j];
        }
    }
    float scale = rsqrtf((float)KVN);
#pragma unroll
    for (int ii = 0; ii < 4; ii++) {
        int i = ty * 4 + ii;
        if (i < UQ) {
#pragma unroll
            for (int j = 0; j < 8; j++)
                g_S1[((size_t)b * UQ + i) * KVN + n0 + tx * 8 + j] =
                    acc[ii][j] * scale;
        }
    }
}

// ---------------- kernel 9: row softmax over S1 --------------------------------
__global__ void softmax_kernel() {
    int row = blockIdx.x;
    float* p = g_S1 + (size_t)row * KVN;
    __shared__ float sred[256];
    int tid = threadIdx.x;

    float m = -3.4e38f;
    for (int i = tid; i < KVN; i += 256) m = fmaxf(m, p[i]);
    sred[tid] = m; __syncthreads();
    for (int s = 128; s > 0; s >>= 1) {
        if (tid < s) sred[tid] = fmaxf(sred[tid], sred[tid + s]);
        __syncthreads();
    }
    m = sred[0];
    __syncthreads();

    float sum = 0.f;
    for (int i = tid; i < KVN; i += 256) {
        float e = expf(p[i] - m);
        p[i] = e;
        sum += e;
    }
    sred[tid] = sum; __syncthreads();
    for (int s = 128; s > 0; s >>= 1) {
        if (tid < s) sred[tid] += sred[tid + s];
        __syncthreads();
    }
    float inv = 1.0f / sred[0];
    for (int i = tid; i < KVN; i += 256) p[i] *= inv;
}

// ---------------- kernel 10: O partials = P @ V (split kv) ---------------------
__global__ void __launch_bounds__(256)
pv_kernel(const float* __restrict__ v) {
    int b = blockIdx.z;
    int s = blockIdx.y;
    int d0 = blockIdx.x * 128;
    int kv0 = s * (KVN / PVS);

    __shared__ float ps[16][64];
    __shared__ float vs[16][128];
    int tid = threadIdx.x;
    int tx = tid & 15, ty = tid >> 4;
    float acc[4][8];
#pragma unroll
    for (int i = 0; i < 4; i++)
#pragma unroll
        for (int j = 0; j < 8; j++) acc[i][j] = 0.f;

    const float* vb = v + (size_t)b * KVN * DD;

    for (int kt = 0; kt < KVN / PVS; kt += 16) {
        __syncthreads();
        if (tid < 240) {
            int i = tid >> 2, hh = (tid & 3) * 4;
            float4 a4 = *(const float4*)(g_S1 + ((size_t)b * UQ + i) * KVN
                                         + kv0 + kt + hh);
            ps[hh + 0][i] = a4.x; ps[hh + 1][i] = a4.y;
            ps[hh + 2][i] = a4.z; ps[hh + 3][i] = a4.w;
        }
        {
            int kkr = tid >> 4, dc = (tid & 15) * 8;
            float4 a4 = *(const float4*)(vb + (size_t)(kv0 + kt + kkr) * DD + d0 + dc);
            float4 b4 = *(const float4*)(vb + (size_t)(kv0 + kt + kkr) * DD + d0 + dc + 4);
            vs[kkr][dc + 0] = a4.x; vs[kkr][dc + 1] = a4.y;
            vs[kkr][dc + 2] = a4.z; vs[kkr][dc + 3] = a4.w;
            vs[kkr][dc + 4] = b4.x; vs[kkr][dc + 5] = b4.y;
            vs[kkr][dc + 6] = b4.z; vs[kkr][dc + 7] = b4.w;
        }
        __syncthreads();
#pragma unroll
        for (int kk = 0; kk < 16; kk++) {
            float a[4], bb[8];
            *(float4*)&a[0]  = *(float4*)&ps[kk][ty * 4];
            *(float4*)&bb[0] = *(float4*)&vs[kk][tx * 8];
            *(float4*)&bb[4] = *(float4*)&vs[kk][tx * 8 + 4];
#pragma unroll
            for (int i = 0; i < 4; i++)
#pragma unroll
                for (int j = 0; j < 8; j++)
                    acc[i][j] += a[i] * bb[j];
        }
    }
#pragma unroll
    for (int ii = 0; ii < 4; ii++) {
        int i = ty * 4 + ii;
        if (i < UQ) {
#pragma unroll
            for (int j = 0; j < 8; j++)
                g_Opart[(((size_t)s * BB + b) * UQ + i) * DD + d0 + tx * 8 + j] =
                    acc[ii][j];
        }
    }
}

// ---------------- kernel 11: reduce PV partials + scatter ----------------------
__global__ void oreduce_kernel(float* __restrict__ out) {
    int idx = blockIdx.x * 256 + threadIdx.x;
    if (idx >= BB * UQ * DD) return;
    int d = idx % DD;
    int rest = idx / DD;
    int i = rest % UQ;
    int b = rest / UQ;
    float s = 0.f;
#pragma unroll
    for (int p = 0; p < PVS; p++)
        s += g_Opart[(((size_t)p * BB + b) * UQ + i) * DD + d];
    int row = g_topidx[b * UQ + i];
    out[((size_t)b * QQ + row) * DD + d] = s;
}

// ---------------- launch --------------------------------------------------------
extern "C" void kernel_launch(void* const* d_in, const int* in_sizes, int n_in,
                              void* d_out, int out_size) {
    const float* q    = (const float*)d_in[0];
    const float* k    = (const float*)d_in[1];
    const float* v    = (const float*)d_in[2];
    const int*   sidx = (const int*)d_in[3];
    float* out = (float*)d_out;
    int U = in_sizes[3] / BB;

    split_kernel<<<(BB * QQ * DD / 4) / 256, 256>>>(q, k);
    zero_count_kernel<<<(BB * KVN + 255) / 256, 256>>>();
    count_kernel<<<(BB * U + 255) / 256, 256>>>(sidx, U);
    wsum_part_kernel<<<dim3(DD / 128, WS_SPLIT, BB), 128>>>(k, v);
    wsum_reduce_kernel<<<(BB * DD + 255) / 256, 256>>>();
    qkmax_tc_kernel<<<dim3(QQ / 128, KVN / 128, BB), 256>>>();
    finalize_kernel<<<(BB * QQ) / 8, 256>>>(q, (float)U);
    topk_kernel<<<BB, 256>>>();
    fill_kernel<<<(BB * QQ * DD / 4) / 256, 256>>>(out);
    logits_kernel<<<dim3(KVN / 128, BB), 256>>>(q, k);
    softmax_kernel<<<BB * UQ, 256>>>();
    pv_kernel<<<dim3(DD / 128, PVS, BB), 256>>>(v);
    oreduce_kernel<<<(BB * UQ * DD + 255) / 256, 256>>>(out);
}

// round 4
// speedup vs baseline: 2.2124x; 1.4699x over previous
#include <cuda_runtime.h>
#include <cuda_bf16.h>
#include <math.h>
#include <stdint.h>

// Problem constants
#define BB    4
#define QQ    2048
#define KVN   2048
#define DD    512
#define UQ    60
#define WS_SPLIT 32
#define KVC   (KVN / WS_SPLIT)   // 64
#define PVS   16
#define CHUNK 32
#define NSTAGE (DD / CHUNK)      // 16

// ---------------- scratch ----------------------------------------------------
__device__ int   g_count[BB * KVN];
__device__ float g_wspart[WS_SPLIT * BB * DD];
__device__ float g_vmpart[WS_SPLIT * BB * DD];
__device__ float g_wsum[BB * DD];
__device__ float g_vmean[BB * DD];
__device__ float g_M[BB * QQ];
__device__ int   g_topidx[BB * UQ];
__device__ float g_S1[(size_t)BB * UQ * KVN];
__device__ float g_Opart[(size_t)PVS * BB * UQ * DD];
__device__ __nv_bfloat16 g_qhi[(size_t)BB * QQ * DD];
__device__ __nv_bfloat16 g_khi[(size_t)BB * KVN * DD];
__device__ float g_Sappr[(size_t)BB * QQ * KVN];   // 67 MB approx scores (masked)

// ---------------- PTX helpers -------------------------------------------------
__device__ __forceinline__ uint32_t smem_u32(const void* p) {
    return (uint32_t)__cvta_generic_to_shared(p);
}
__device__ __forceinline__ void cpa16(uint32_t saddr, const void* g) {
    asm volatile("cp.async.cg.shared.global [%0], [%1], 16;" :: "r"(saddr), "l"(g));
}
__device__ __forceinline__ void ldsm4(uint32_t& r0, uint32_t& r1, uint32_t& r2,
                                      uint32_t& r3, uint32_t addr) {
    asm volatile("ldmatrix.sync.aligned.m8n8.x4.shared.b16 {%0,%1,%2,%3}, [%4];"
                 : "=r"(r0), "=r"(r1), "=r"(r2), "=r"(r3) : "r"(addr));
}
__device__ __forceinline__ void mma16816(float* c, const uint32_t* a,
                                         uint32_t b0, uint32_t b1) {
    asm volatile(
        "mma.sync.aligned.m16n8k16.row.col.f32.bf16.bf16.f32 "
        "{%0,%1,%2,%3}, {%4,%5,%6,%7}, {%8,%9}, {%0,%1,%2,%3};"
        : "+f"(c[0]), "+f"(c[1]), "+f"(c[2]), "+f"(c[3])
        : "r"(a[0]), "r"(a[1]), "r"(a[2]), "r"(a[3]), "r"(b0), "r"(b1));
}

// ---------------- kernel 0: bf16 hi of q and k ---------------------------------
__global__ void split_kernel(const float* __restrict__ q, const float* __restrict__ k) {
    size_t i = (size_t)blockIdx.x * 256 + threadIdx.x;   // float4 index
    float4 a = ((const float4*)q)[i];
    __nv_bfloat162 h01, h23;
    h01.x = __float2bfloat16(a.x); h01.y = __float2bfloat16(a.y);
    h23.x = __float2bfloat16(a.z); h23.y = __float2bfloat16(a.w);
    ((__nv_bfloat162*)g_qhi)[i * 2] = h01; ((__nv_bfloat162*)g_qhi)[i * 2 + 1] = h23;

    float4 bvec = ((const float4*)k)[i];
    h01.x = __float2bfloat16(bvec.x); h01.y = __float2bfloat16(bvec.y);
    h23.x = __float2bfloat16(bvec.z); h23.y = __float2bfloat16(bvec.w);
    ((__nv_bfloat162*)g_khi)[i * 2] = h01; ((__nv_bfloat162*)g_khi)[i * 2 + 1] = h23;
}

// ---------------- kernels 1,2: counts -----------------------------------------
__global__ void zero_count_kernel() {
    int i = blockIdx.x * blockDim.x + threadIdx.x;
    if (i < BB * KVN) g_count[i] = 0;
}
__global__ void count_kernel(const int* __restrict__ sidx, int U) {
    int i = blockIdx.x * blockDim.x + threadIdx.x;
    if (i < BB * U) {
        int b = i / U;
        atomicAdd(&g_count[b * KVN + sidx[i]], 1);
    }
}

// ---------------- kernel 3: weighted key sum + v mean --------------------------
__global__ void wsum_part_kernel(const float* __restrict__ k,
                                 const float* __restrict__ v) {
    int b = blockIdx.z;
    int s = blockIdx.y;
    int d = blockIdx.x * 128 + threadIdx.x;

    __shared__ float cntf[KVC];
    if (threadIdx.x < KVC)
        cntf[threadIdx.x] = (float)g_count[b * KVN + s * KVC + threadIdx.x];
    __syncthreads();

    const float* kp = k + ((size_t)b * KVN + (size_t)s * KVC) * DD + d;
    const float* vp = v + ((size_t)b * KVN + (size_t)s * KVC) * DD + d;
    float ws = 0.f, vm = 0.f;
#pragma unroll 8
    for (int j = 0; j < KVC; j++) {
        ws += cntf[j] * kp[(size_t)j * DD];
        vm += vp[(size_t)j * DD];
    }
    g_wspart[((size_t)s * BB + b) * DD + d] = ws;
    g_vmpart[((size_t)s * BB + b) * DD + d] = vm;
}

__global__ void wsum_reduce_kernel() {
    int idx = blockIdx.x * blockDim.x + threadIdx.x;
    if (idx >= BB * DD) return;
    int b = idx / DD, d = idx % DD;
    float ws = 0.f, vm = 0.f;
#pragma unroll
    for (int s = 0; s < WS_SPLIT; s++) {
        ws += g_wspart[((size_t)s * BB + b) * DD + d];
        vm += g_vmpart[((size_t)s * BB + b) * DD + d];
    }
    g_wsum[idx] = ws;
    g_vmean[idx] = vm * (1.0f / KVN);
}

// ---------------- kernel 4: approx QK^T (bf16 HMMA), masked store --------------
// grid (16,16,4), block 256 (8 warps: 2m x 4n), warp tile 64x32, K-step 32.
__global__ void __launch_bounds__(256, 2)
qkmax_tc_kernel() {
    __shared__ __nv_bfloat16 sA[2][128][40];
    __shared__ __nv_bfloat16 sB[2][128][40];
    __shared__ int cmask[128];

    const int tid = threadIdx.x, lane = tid & 31, warp = tid >> 5;
    const int wm = warp >> 2, wn = warp & 3;
    const int b = blockIdx.z;
    const int m0 = blockIdx.x * 128, n0 = blockIdx.y * 128;

    const __nv_bfloat16* qh = g_qhi + (size_t)b * QQ * DD;
    const __nv_bfloat16* kh = g_khi + (size_t)b * KVN * DD;

    if (tid < 128) cmask[tid] = g_count[b * KVN + n0 + tid];

    const int lrow = tid >> 1, lhalf = tid & 1;
    const size_t gaoff = (size_t)(m0 + lrow) * DD + lhalf * 8;
    const size_t gboff = (size_t)(n0 + lrow) * DD + lhalf * 8;
    const uint32_t saA = smem_u32(&sA[0][lrow][lhalf * 8]);
    const uint32_t saB = smem_u32(&sB[0][lrow][lhalf * 8]);
    const uint32_t BUFSTRIDE = 128 * 40 * 2;   // 10240 bytes

    const int lr = lane & 15;
    const int lc8 = (lane >> 4) * 8;
    const uint32_t aAh = smem_u32(&sA[0][wm * 64 + lr][lc8]);
    const uint32_t aBh = smem_u32(&sB[0][wn * 32 + lr][lc8]);

    float acc[4][4][4];
#pragma unroll
    for (int mt = 0; mt < 4; mt++)
#pragma unroll
        for (int nt = 0; nt < 4; nt++)
#pragma unroll
            for (int r = 0; r < 4; r++) acc[mt][nt][r] = 0.f;

    auto issue = [&](int ks) {
        uint32_t bo = (uint32_t)(ks & 1) * BUFSTRIDE;
        int dt = ks * CHUNK;
        cpa16(saA + bo,      qh + gaoff + dt);
        cpa16(saA + bo + 32, qh + gaoff + dt + 16);
        cpa16(saB + bo,      kh + gboff + dt);
        cpa16(saB + bo + 32, kh + gboff + dt + 16);
        asm volatile("cp.async.commit_group;");
    };

    issue(0);
#pragma unroll 1
    for (int ks = 0; ks < NSTAGE; ks++) {
        if (ks < NSTAGE - 1) {
            issue(ks + 1);
            asm volatile("cp.async.wait_group 1;");
        } else {
            asm volatile("cp.async.wait_group 0;");
        }
        __syncthreads();

        uint32_t bo = (uint32_t)(ks & 1) * BUFSTRIDE;
#pragma unroll
        for (int kh2 = 0; kh2 < 2; kh2++) {
            uint32_t ko = bo + kh2 * 32;   // +16 bf16 elems
            uint32_t a[4][4], bf[2][4];
#pragma unroll
            for (int mt = 0; mt < 4; mt++)
                ldsm4(a[mt][0], a[mt][1], a[mt][2], a[mt][3], aAh + ko + mt * 1280);
#pragma unroll
            for (int nc = 0; nc < 2; nc++)
                ldsm4(bf[nc][0], bf[nc][1], bf[nc][2], bf[nc][3], aBh + ko + nc * 1280);
#pragma unroll
            for (int mt = 0; mt < 4; mt++)
#pragma unroll
                for (int nt = 0; nt < 4; nt++) {
                    int nc = nt >> 1, s = nt & 1;
                    mma16816(acc[mt][nt], a[mt], bf[nc][s], bf[nc][2 + s]);
                }
        }
        __syncthreads();
    }

    // ---- epilogue: masked store of approx scores ----
    float* srow = g_Sappr + ((size_t)b * QQ + m0) * KVN + n0;
#pragma unroll
    for (int nt = 0; nt < 4; nt++) {
        int c = wn * 32 + nt * 8 + (lane & 3) * 2;
        bool ok0 = cmask[c] > 0, ok1 = cmask[c + 1] > 0;
#pragma unroll
        for (int mt = 0; mt < 4; mt++) {
            int r0 = wm * 64 + mt * 16 + (lane >> 2);
            float2 v0, v1;
            v0.x = ok0 ? acc[mt][nt][0] : -3.0e38f;
            v0.y = ok1 ? acc[mt][nt][1] : -3.0e38f;
            v1.x = ok0 ? acc[mt][nt][2] : -3.0e38f;
            v1.y = ok1 ? acc[mt][nt][3] : -3.0e38f;
            *(float2*)(srow + (size_t)r0 * KVN + c)       = v0;
            *(float2*)(srow + (size_t)(r0 + 8) * KVN + c) = v1;
        }
    }
}

// ---------------- kernel 5: refine — exact max + M -----------------------------
// 1 warp per query row: approx-max scan, window candidates, exact fp32 rescore.
__global__ void refine_kernel(const float* __restrict__ q,
                              const float* __restrict__ k, float Uf) {
    int row = blockIdx.x * 8 + (threadIdx.x >> 5);   // b*QQ + qi
    int lane = threadIdx.x & 31;
    if (row >= BB * QQ) return;
    int b = row / QQ;
    const float* srow = g_Sappr + (size_t)row * KVN;

    // pass 1: approx row max
    float mx = -3.0e38f;
#pragma unroll 8
    for (int j = 0; j < KVN / 32; j++)
        mx = fmaxf(mx, srow[j * 32 + lane]);
#pragma unroll
    for (int off = 16; off > 0; off >>= 1)
        mx = fmaxf(mx, __shfl_xor_sync(0xffffffffu, mx, off));
    float thr = mx - 1.0f;

    // q . wsum
    const float* qr = q + (size_t)row * DD;
    const float* ws = g_wsum + b * DD;
    float qw = 0.f;
#pragma unroll
    for (int t = 0; t < DD / 32; t++)
        qw += qr[t * 32 + lane] * ws[t * 32 + lane];
#pragma unroll
    for (int off = 16; off > 0; off >>= 1)
        qw += __shfl_xor_sync(0xffffffffu, qw, off);

    // pass 2: candidates + exact fp32 rescore
    const float* kb = k + (size_t)b * KVN * DD;
    float best = -3.0e38f;
    for (int j = 0; j < KVN / 32; j++) {
        unsigned msk = __ballot_sync(0xffffffffu, srow[j * 32 + lane] >= thr);
        while (msk) {
            int src = __ffs(msk) - 1;
            msk &= msk - 1;
            int col = j * 32 + src;
            const float* kr = kb + (size_t)col * DD;
            float d = 0.f;
#pragma unroll
            for (int t = 0; t < DD / 32; t++)
                d += qr[t * 32 + lane] * kr[t * 32 + lane];
#pragma unroll
            for (int off = 16; off > 0; off >>= 1)
                d += __shfl_xor_sync(0xffffffffu, d, off);
            best = fmaxf(best, d);
        }
    }
    if (lane == 0) g_M[row] = best - qw / Uf;
}

// ---------------- kernel 6: top-60 per batch (u64 argmax) -----------------------
__global__ void topk_kernel() {
    int b = blockIdx.x;
    __shared__ float vals[QQ];
    __shared__ unsigned long long wred[8];
    int tid = threadIdx.x;
    for (int i = tid; i < QQ; i += 256) vals[i] = g_M[b * QQ + i];
    __syncthreads();
    for (int it = 0; it < UQ; it++) {
        unsigned long long best = 0ull;
        for (int i = tid; i < QQ; i += 256) {
            uint32_t u = __float_as_uint(vals[i]);
            u = (u & 0x80000000u) ? ~u : (u | 0x80000000u);
            unsigned long long cand =
                ((unsigned long long)u << 32) | (unsigned long long)(QQ - 1 - i);
            best = (cand > best) ? cand : best;
        }
#pragma unroll
        for (int off = 16; off > 0; off >>= 1) {
            unsigned long long o = __shfl_xor_sync(0xffffffffu, best, off);
            best = (o > best) ? o : best;
        }
        if ((tid & 31) == 0) wred[tid >> 5] = best;
        __syncthreads();
        if (tid == 0) {
            unsigned long long m = wred[0];
#pragma unroll
            for (int w = 1; w < 8; w++) m = (wred[w] > m) ? wred[w] : m;
            int i = QQ - 1 - (int)(m & 0xFFFFFFFFull);
            g_topidx[b * UQ + it] = i;
            vals[i] = -3.4e38f;
        }
        __syncthreads();
    }
}

// ---------------- kernel 7: fill output with v-mean ------------------------------
__global__ void fill_kernel(float* __restrict__ out) {
    size_t f = (size_t)blockIdx.x * 256 + threadIdx.x;
    int d4 = (int)(f & (DD / 4 - 1));
    size_t row = f >> 7;
    int b = (int)(row >> 11);
    float4 val = *(const float4*)(g_vmean + b * DD + d4 * 4);
    ((float4*)out)[f] = val;
}

// ---------------- kernel 8: logits S1 = q_bar @ k^T * scale ----------------------
__global__ void __launch_bounds__(256)
logits_kernel(const float* __restrict__ q, const float* __restrict__ k) {
    int b = blockIdx.y;
    int n0 = blockIdx.x * 128;
    __shared__ int   tix[UQ];
    __shared__ float qs2[16][64];
    __shared__ float ks2[16][128];
    int tid = threadIdx.x;
    if (tid < UQ) tix[tid] = g_topidx[b * UQ + tid];

    int tx = tid & 15, ty = tid >> 4;
    float acc[4][8];
#pragma unroll
    for (int i = 0; i < 4; i++)
#pragma unroll
        for (int j = 0; j < 8; j++) acc[i][j] = 0.f;

    const float* qb = q + (size_t)b * QQ * DD;
    const float* kb = k + (size_t)b * KVN * DD;

    for (int dt = 0; dt < DD; dt += 16) {
        __syncthreads();
        if (tid < 240) {
            int i = tid >> 2, hh = (tid & 3) * 4;
            float4 v4 = *(const float4*)(qb + (size_t)tix[i] * DD + dt + hh);
            qs2[hh + 0][i] = v4.x; qs2[hh + 1][i] = v4.y;
            qs2[hh + 2][i] = v4.z; qs2[hh + 3][i] = v4.w;
        }
        {
            int r2 = tid >> 1, h2 = (tid & 1) * 8;
            float4 a4 = *(const float4*)(kb + (size_t)(n0 + r2) * DD + dt + h2);
            float4 b4 = *(const float4*)(kb + (size_t)(n0 + r2) * DD + dt + h2 + 4);
            ks2[h2 + 0][r2] = a4.x; ks2[h2 + 1][r2] = a4.y;
            ks2[h2 + 2][r2] = a4.z; ks2[h2 + 3][r2] = a4.w;
            ks2[h2 + 4][r2] = b4.x; ks2[h2 + 5][r2] = b4.y;
            ks2[h2 + 6][r2] = b4.z; ks2[h2 + 7][r2] = b4.w;
        }
        __syncthreads();
#pragma unroll
        for (int kk = 0; kk < 16; kk++) {
            float a[4], bb[8];
            *(float4*)&a[0]  = *(float4*)&qs2[kk][ty * 4];
            *(float4*)&bb[0] = *(float4*)&ks2[kk][tx * 8];
            *(float4*)&bb[4] = *(float4*)&ks2[kk][tx * 8 + 4];
#pragma unroll
            for (int i = 0; i < 4; i++)
#pragma unroll
                for (int j = 0; j < 8; j++)
                    acc[i][j] += a[i] * bb[j];
        }
    }
    float scale = rsqrtf((float)KVN);
#pragma unroll
    for (int ii = 0; ii < 4; ii++) {
        int i = ty * 4 + ii;
        if (i < UQ) {
#pragma unroll
            for (int j = 0; j < 8; j++)
                g_S1[((size_t)b * UQ + i) * KVN + n0 + tx * 8 + j] =
                    acc[ii][j] * scale;
        }
    }
}

// ---------------- kernel 9: row softmax over S1 ----------------------------------
__global__ void softmax_kernel() {
    int row = blockIdx.x;
    float* p = g_S1 + (size_t)row * KVN;
    __shared__ float sred[256];
    int tid = threadIdx.x;

    float m = -3.4e38f;
    for (int i = tid; i < KVN; i += 256) m = fmaxf(m, p[i]);
    sred[tid] = m; __syncthreads();
    for (int s = 128; s > 0; s >>= 1) {
        if (tid < s) sred[tid] = fmaxf(sred[tid], sred[tid + s]);
        __syncthreads();
    }
    m = sred[0];
    __syncthreads();

    float sum = 0.f;
    for (int i = tid; i < KVN; i += 256) {
        float e = expf(p[i] - m);
        p[i] = e;
        sum += e;
    }
    sred[tid] = sum; __syncthreads();
    for (int s = 128; s > 0; s >>= 1) {
        if (tid < s) sred[tid] += sred[tid + s];
        __syncthreads();
    }
    float inv = 1.0f / sred[0];
    for (int i = tid; i < KVN; i += 256) p[i] *= inv;
}

// ---------------- kernel 10: O partials = P @ V (split kv) -----------------------
__global__ void __launch_bounds__(256)
pv_kernel(const float* __restrict__ v) {
    int b = blockIdx.z;
    int s = blockIdx.y;
    int d0 = blockIdx.x * 128;
    int kv0 = s * (KVN / PVS);

    __shared__ float ps[16][64];
    __shared__ float vs[16][128];
    int tid = threadIdx.x;
    int tx = tid & 15, ty = tid >> 4;
    float acc[4][8];
#pragma unroll
    for (int i = 0; i < 4; i++)
#pragma unroll
        for (int j = 0; j < 8; j++) acc[i][j] = 0.f;

    const float* vb = v + (size_t)b * KVN * DD;

    for (int kt = 0; kt < KVN / PVS; kt += 16) {
        __syncthreads();
        if (tid < 240) {
            int i = tid >> 2, hh = (tid & 3) * 4;
            float4 a4 = *(const float4*)(g_S1 + ((size_t)b * UQ + i) * KVN
                                         + kv0 + kt + hh);
            ps[hh + 0][i] = a4.x; ps[hh + 1][i] = a4.y;
            ps[hh + 2][i] = a4.z; ps[hh + 3][i] = a4.w;
        }
        {
            int kkr = tid >> 4, dc = (tid & 15) * 8;
            float4 a4 = *(const float4*)(vb + (size_t)(kv0 + kt + kkr) * DD + d0 + dc);
            float4 b4 = *(const float4*)(vb + (size_t)(kv0 + kt + kkr) * DD + d0 + dc + 4);
            vs[kkr][dc + 0] = a4.x; vs[kkr][dc + 1] = a4.y;
            vs[kkr][dc + 2] = a4.z; vs[kkr][dc + 3] = a4.w;
            vs[kkr][dc + 4] = b4.x; vs[kkr][dc + 5] = b4.y;
            vs[kkr][dc + 6] = b4.z; vs[kkr][dc + 7] = b4.w;
        }
        __syncthreads();
#pragma unroll
        for (int kk = 0; kk < 16; kk++) {
            float a[4], bb[8];
            *(float4*)&a[0]  = *(float4*)&ps[kk][ty * 4];
            *(float4*)&bb[0] = *(float4*)&vs[kk][tx * 8];
            *(float4*)&bb[4] = *(float4*)&vs[kk][tx * 8 + 4];
#pragma unroll
            for (int i = 0; i < 4; i++)
#pragma unroll
                for (int j = 0; j < 8; j++)
                    acc[i][j] += a[i] * bb[j];
        }
    }
#pragma unroll
    for (int ii = 0; ii < 4; ii++) {
        int i = ty * 4 + ii;
        if (i < UQ) {
#pragma unroll
            for (int j = 0; j < 8; j++)
                g_Opart[(((size_t)s * BB + b) * UQ + i) * DD + d0 + tx * 8 + j] =
                    acc[ii][j];
        }
    }
}

// ---------------- kernel 11: reduce PV partials + scatter ------------------------
__global__ void oreduce_kernel(float* __restrict__ out) {
    int idx = blockIdx.x * 256 + threadIdx.x;
    if (idx >= BB * UQ * DD) return;
    int d = idx % DD;
    int rest = idx / DD;
    int i = rest % UQ;
    int b = rest / UQ;
    float s = 0.f;
#pragma unroll
    for (int p = 0; p < PVS; p++)
        s += g_Opart[(((size_t)p * BB + b) * UQ + i) * DD + d];
    int row = g_topidx[b * UQ + i];
    out[((size_t)b * QQ + row) * DD + d] = s;
}

// ---------------- launch ----------------------------------------------------------
extern "C" void kernel_launch(void* const* d_in, const int* in_sizes, int n_in,
                              void* d_out, int out_size) {
    const float* q    = (const float*)d_in[0];
    const float* k    = (const float*)d_in[1];
    const float* v    = (const float*)d_in[2];
    const int*   sidx = (const int*)d_in[3];
    float* out = (float*)d_out;
    int U = in_sizes[3] / BB;

    split_kernel<<<(BB * QQ * DD / 4) / 256, 256>>>(q, k);
    zero_count_kernel<<<(BB * KVN + 255) / 256, 256>>>();
    count_kernel<<<(BB * U + 255) / 256, 256>>>(sidx, U);
    wsum_part_kernel<<<dim3(DD / 128, WS_SPLIT, BB), 128>>>(k, v);
    wsum_reduce_kernel<<<(BB * DD + 255) / 256, 256>>>();
    qkmax_tc_kernel<<<dim3(QQ / 128, KVN / 128, BB), 256>>>();
    refine_kernel<<<(BB * QQ) / 8, 256>>>(q, k, (float)U);
    topk_kernel<<<BB, 256>>>();
    fill_kernel<<<(BB * QQ * DD / 4) / 256, 256>>>(out);
    logits_kernel<<<dim3(KVN / 128, BB), 256>>>(q, k);
    softmax_kernel<<<BB * UQ, 256>>>();
    pv_kernel<<<dim3(DD / 128, PVS, BB), 256>>>(v);
    oreduce_kernel<<<(BB * UQ * DD + 255) / 256, 256>>>(out);
}

// round 5
// speedup vs baseline: 2.5461x; 1.1508x over previous
#include <cuda_runtime.h>
#include <cuda_bf16.h>
#include <math.h>
#include <stdint.h>

// Problem constants
#define BB    4
#define QQ    2048
#define KVN   2048
#define DD    512
#define UQ    60
#define NTILES (KVN / 128)       // 16
#define WS_SPLIT 32
#define KVC   (KVN / WS_SPLIT)   // 64
#define PVS   16
#define CHUNK 32
#define NSTAGE (DD / CHUNK)      // 16
#define WWIN  1.0f               // rescue window (6-sigma bf16 dot error ~0.4)

// ---------------- scratch ----------------------------------------------------
__device__ int   g_count[BB * KVN];
__device__ float g_wspart[WS_SPLIT * BB * DD];
__device__ float g_vmpart[WS_SPLIT * BB * DD];
__device__ float g_wsum[BB * DD];
__device__ float g_vmean[BB * DD];
__device__ float g_M[BB * QQ];
__device__ float g_Mpart[BB * QQ * NTILES];
__device__ uint32_t g_cand[(size_t)BB * QQ * NTILES * 4];   // 128-bit masks, 2 MB
__device__ int   g_topidx[BB * UQ];
__device__ float g_S1[(size_t)BB * UQ * KVN];
__device__ float g_Opart[(size_t)PVS * BB * UQ * DD];
__device__ __nv_bfloat16 g_qhi[(size_t)BB * QQ * DD];
__device__ __nv_bfloat16 g_khi[(size_t)BB * KVN * DD];

// ---------------- PTX helpers -------------------------------------------------
__device__ __forceinline__ uint32_t smem_u32(const void* p) {
    return (uint32_t)__cvta_generic_to_shared(p);
}
__device__ __forceinline__ void cpa16(uint32_t saddr, const void* g) {
    asm volatile("cp.async.cg.shared.global [%0], [%1], 16;" :: "r"(saddr), "l"(g));
}
__device__ __forceinline__ void ldsm4(uint32_t& r0, uint32_t& r1, uint32_t& r2,
                                      uint32_t& r3, uint32_t addr) {
    asm volatile("ldmatrix.sync.aligned.m8n8.x4.shared.b16 {%0,%1,%2,%3}, [%4];"
                 : "=r"(r0), "=r"(r1), "=r"(r2), "=r"(r3) : "r"(addr));
}
__device__ __forceinline__ void mma16816(float* c, const uint32_t* a,
                                         uint32_t b0, uint32_t b1) {
    asm volatile(
        "mma.sync.aligned.m16n8k16.row.col.f32.bf16.bf16.f32 "
        "{%0,%1,%2,%3}, {%4,%5,%6,%7}, {%8,%9}, {%0,%1,%2,%3};"
        : "+f"(c[0]), "+f"(c[1]), "+f"(c[2]), "+f"(c[3])
        : "r"(a[0]), "r"(a[1]), "r"(a[2]), "r"(a[3]), "r"(b0), "r"(b1));
}

// ---------------- kernel 0: bf16 hi of q and k ---------------------------------
__global__ void split_kernel(const float* __restrict__ q, const float* __restrict__ k) {
    size_t i = (size_t)blockIdx.x * 256 + threadIdx.x;   // float4 index
    float4 a = ((const float4*)q)[i];
    __nv_bfloat162 h01, h23;
    h01.x = __float2bfloat16(a.x); h01.y = __float2bfloat16(a.y);
    h23.x = __float2bfloat16(a.z); h23.y = __float2bfloat16(a.w);
    ((__nv_bfloat162*)g_qhi)[i * 2] = h01; ((__nv_bfloat162*)g_qhi)[i * 2 + 1] = h23;

    float4 bvec = ((const float4*)k)[i];
    h01.x = __float2bfloat16(bvec.x); h01.y = __float2bfloat16(bvec.y);
    h23.x = __float2bfloat16(bvec.z); h23.y = __float2bfloat16(bvec.w);
    ((__nv_bfloat162*)g_khi)[i * 2] = h01; ((__nv_bfloat162*)g_khi)[i * 2 + 1] = h23;
}

// ---------------- kernels 1,2: counts -----------------------------------------
__global__ void zero_count_kernel() {
    int i = blockIdx.x * blockDim.x + threadIdx.x;
    if (i < BB * KVN) g_count[i] = 0;
}
__global__ void count_kernel(const int* __restrict__ sidx, int U) {
    int i = blockIdx.x * blockDim.x + threadIdx.x;
    if (i < BB * U) {
        int b = i / U;
        atomicAdd(&g_count[b * KVN + sidx[i]], 1);
    }
}

// ---------------- kernel 3: weighted key sum + v mean --------------------------
__global__ void wsum_part_kernel(const float* __restrict__ k,
                                 const float* __restrict__ v) {
    int b = blockIdx.z;
    int s = blockIdx.y;
    int d = blockIdx.x * 128 + threadIdx.x;

    __shared__ float cntf[KVC];
    if (threadIdx.x < KVC)
        cntf[threadIdx.x] = (float)g_count[b * KVN + s * KVC + threadIdx.x];
    __syncthreads();

    const float* kp = k + ((size_t)b * KVN + (size_t)s * KVC) * DD + d;
    const float* vp = v + ((size_t)b * KVN + (size_t)s * KVC) * DD + d;
    float ws = 0.f, vm = 0.f;
#pragma unroll 8
    for (int j = 0; j < KVC; j++) {
        ws += cntf[j] * kp[(size_t)j * DD];
        vm += vp[(size_t)j * DD];
    }
    g_wspart[((size_t)s * BB + b) * DD + d] = ws;
    g_vmpart[((size_t)s * BB + b) * DD + d] = vm;
}

__global__ void wsum_reduce_kernel() {
    int idx = blockIdx.x * blockDim.x + threadIdx.x;
    if (idx >= BB * DD) return;
    int b = idx / DD, d = idx % DD;
    float ws = 0.f, vm = 0.f;
#pragma unroll
    for (int s = 0; s < WS_SPLIT; s++) {
        ws += g_wspart[((size_t)s * BB + b) * DD + d];
        vm += g_vmpart[((size_t)s * BB + b) * DD + d];
    }
    g_wsum[idx] = ws;
    g_vmean[idx] = vm * (1.0f / KVN);
}

// ---------------- kernel 4: approx QK^T (bf16 HMMA) -> rowmax + cand bits ------
// grid (16,16,4), block 256 (8 warps: 2m x 4n), warp tile 64x32, K-step 32.
__global__ void __launch_bounds__(256, 2)
qkmax_tc_kernel() {
    __shared__ __nv_bfloat16 sA[2][128][40];
    __shared__ __nv_bfloat16 sB[2][128][40];
    __shared__ int      cmask[128];
    __shared__ float    smax[128][4];
    __shared__ float    rmax[128];
    __shared__ uint32_t bits[128][4];

    const int tid = threadIdx.x, lane = tid & 31, warp = tid >> 5;
    const int wm = warp >> 2, wn = warp & 3;
    const int b = blockIdx.z;
    const int m0 = blockIdx.x * 128, n0 = blockIdx.y * 128;

    const __nv_bfloat16* qh = g_qhi + (size_t)b * QQ * DD;
    const __nv_bfloat16* kh = g_khi + (size_t)b * KVN * DD;

    if (tid < 128) {
        cmask[tid] = g_count[b * KVN + n0 + tid];
        bits[tid][0] = 0u; bits[tid][1] = 0u; bits[tid][2] = 0u; bits[tid][3] = 0u;
    }

    const int lrow = tid >> 1, lhalf = tid & 1;
    const size_t gaoff = (size_t)(m0 + lrow) * DD + lhalf * 8;
    const size_t gboff = (size_t)(n0 + lrow) * DD + lhalf * 8;
    const uint32_t saA = smem_u32(&sA[0][lrow][lhalf * 8]);
    const uint32_t saB = smem_u32(&sB[0][lrow][lhalf * 8]);
    const uint32_t BUFSTRIDE = 128 * 40 * 2;   // 10240 bytes

    const int lr = lane & 15;
    const int lc8 = (lane >> 4) * 8;
    const uint32_t aAh = smem_u32(&sA[0][wm * 64 + lr][lc8]);
    const uint32_t aBh = smem_u32(&sB[0][wn * 32 + lr][lc8]);

    float acc[4][4][4];
#pragma unroll
    for (int mt = 0; mt < 4; mt++)
#pragma unroll
        for (int nt = 0; nt < 4; nt++)
#pragma unroll
            for (int r = 0; r < 4; r++) acc[mt][nt][r] = 0.f;

    auto issue = [&](int ks) {
        uint32_t bo = (uint32_t)(ks & 1) * BUFSTRIDE;
        int dt = ks * CHUNK;
        cpa16(saA + bo,      qh + gaoff + dt);
        cpa16(saA + bo + 32, qh + gaoff + dt + 16);
        cpa16(saB + bo,      kh + gboff + dt);
        cpa16(saB + bo + 32, kh + gboff + dt + 16);
        asm volatile("cp.async.commit_group;");
    };

    issue(0);
#pragma unroll 1
    for (int ks = 0; ks < NSTAGE; ks++) {
        if (ks < NSTAGE - 1) {
            issue(ks + 1);
            asm volatile("cp.async.wait_group 1;");
        } else {
            asm volatile("cp.async.wait_group 0;");
        }
        __syncthreads();

        uint32_t bo = (uint32_t)(ks & 1) * BUFSTRIDE;
#pragma unroll
        for (int kh2 = 0; kh2 < 2; kh2++) {
            uint32_t ko = bo + kh2 * 32;
            uint32_t a[4][4], bf[2][4];
#pragma unroll
            for (int mt = 0; mt < 4; mt++)
                ldsm4(a[mt][0], a[mt][1], a[mt][2], a[mt][3], aAh + ko + mt * 1280);
#pragma unroll
            for (int nc = 0; nc < 2; nc++)
                ldsm4(bf[nc][0], bf[nc][1], bf[nc][2], bf[nc][3], aBh + ko + nc * 1280);
#pragma unroll
            for (int mt = 0; mt < 4; mt++)
#pragma unroll
                for (int nt = 0; nt < 4; nt++) {
                    int nc = nt >> 1, s = nt & 1;
                    mma16816(acc[mt][nt], a[mt], bf[nc][s], bf[nc][2 + s]);
                }
        }
        __syncthreads();
    }

    // ---- epilogue: masked row-max + candidate bitmask ----
    // apply count mask in-register
#pragma unroll
    for (int nt = 0; nt < 4; nt++) {
        int c = wn * 32 + nt * 8 + (lane & 3) * 2;
        bool ok0 = cmask[c] > 0, ok1 = cmask[c + 1] > 0;
#pragma unroll
        for (int mt = 0; mt < 4; mt++) {
            if (!ok0) { acc[mt][nt][0] = -3.0e38f; acc[mt][nt][2] = -3.0e38f; }
            if (!ok1) { acc[mt][nt][1] = -3.0e38f; acc[mt][nt][3] = -3.0e38f; }
        }
    }
    // warp row maxes
    float rm[8];
#pragma unroll
    for (int i = 0; i < 8; i++) rm[i] = -3.0e38f;
#pragma unroll
    for (int nt = 0; nt < 4; nt++)
#pragma unroll
        for (int mt = 0; mt < 4; mt++) {
            rm[mt * 2]     = fmaxf(rm[mt * 2],     fmaxf(acc[mt][nt][0], acc[mt][nt][1]));
            rm[mt * 2 + 1] = fmaxf(rm[mt * 2 + 1], fmaxf(acc[mt][nt][2], acc[mt][nt][3]));
        }
#pragma unroll
    for (int i = 0; i < 8; i++) {
        rm[i] = fmaxf(rm[i], __shfl_xor_sync(0xffffffffu, rm[i], 1));
        rm[i] = fmaxf(rm[i], __shfl_xor_sync(0xffffffffu, rm[i], 2));
    }
    if ((lane & 3) == 0) {
        int g = lane >> 2;
#pragma unroll
        for (int mt = 0; mt < 4; mt++) {
            smax[wm * 64 + mt * 16 + g][wn]     = rm[mt * 2];
            smax[wm * 64 + mt * 16 + g + 8][wn] = rm[mt * 2 + 1];
        }
    }
    __syncthreads();
    if (tid < 128)
        rmax[tid] = fmaxf(fmaxf(smax[tid][0], smax[tid][1]),
                          fmaxf(smax[tid][2], smax[tid][3]));
    __syncthreads();

    // candidate bits: score >= rowmax - WWIN
    {
        int g = lane >> 2;
#pragma unroll
        for (int mt = 0; mt < 4; mt++) {
            int r0 = wm * 64 + mt * 16 + g;
            float t0 = rmax[r0] - WWIN, t1 = rmax[r0 + 8] - WWIN;
#pragma unroll
            for (int nt = 0; nt < 4; nt++) {
                int c = wn * 32 + nt * 8 + (lane & 3) * 2;
                if (acc[mt][nt][0] >= t0) atomicOr(&bits[r0][c >> 5], 1u << (c & 31));
                if (acc[mt][nt][1] >= t0) atomicOr(&bits[r0][(c + 1) >> 5], 1u << ((c + 1) & 31));
                if (acc[mt][nt][2] >= t1) atomicOr(&bits[r0 + 8][c >> 5], 1u << (c & 31));
                if (acc[mt][nt][3] >= t1) atomicOr(&bits[r0 + 8][(c + 1) >> 5], 1u << ((c + 1) & 31));
            }
        }
    }
    __syncthreads();
    if (tid < 128) {
        size_t ro = ((size_t)b * QQ + m0 + tid) * NTILES + blockIdx.y;
        g_Mpart[ro] = rmax[tid];
        *(uint4*)&g_cand[ro * 4] = *(uint4*)&bits[tid][0];
    }
}

// ---------------- kernel 5: refine — exact max + M -----------------------------
// 1 warp per query row: tile filter + exact fp32 rescore of candidate bits.
__global__ void refine_kernel(const float* __restrict__ q,
                              const float* __restrict__ k, float Uf) {
    int row = blockIdx.x * 8 + (threadIdx.x >> 5);   // b*QQ + qi
    int lane = threadIdx.x & 31;
    if (row >= BB * QQ) return;
    int b = row / QQ;

    const float* mp = g_Mpart + (size_t)row * NTILES;
    float gmax = -3.0e38f;
#pragma unroll
    for (int t = 0; t < NTILES; t++) gmax = fmaxf(gmax, mp[t]);
    float thr = gmax - WWIN;

    // q . wsum
    const float* qr = q + (size_t)row * DD;
    const float* ws = g_wsum + b * DD;
    float qw = 0.f;
#pragma unroll
    for (int t = 0; t < DD / 32; t++)
        qw += qr[t * 32 + lane] * ws[t * 32 + lane];
#pragma unroll
    for (int off = 16; off > 0; off >>= 1)
        qw += __shfl_xor_sync(0xffffffffu, qw, off);

    const float* kb = k + (size_t)b * KVN * DD;
    float best = -3.0e38f;
#pragma unroll 1
    for (int t = 0; t < NTILES; t++) {
        if (mp[t] < thr) continue;
        const uint32_t* cw = g_cand + ((size_t)row * NTILES + t) * 4;
#pragma unroll
        for (int w = 0; w < 4; w++) {
            uint32_t m = cw[w];
            while (m) {
                int bit = __ffs(m) - 1;
                m &= m - 1;
                int col = t * 128 + w * 32 + bit;
                const float* kr = kb + (size_t)col * DD;
                float d = 0.f;
#pragma unroll
                for (int tt = 0; tt < DD / 32; tt++)
                    d += qr[tt * 32 + lane] * kr[tt * 32 + lane];
#pragma unroll
                for (int off = 16; off > 0; off >>= 1)
                    d += __shfl_xor_sync(0xffffffffu, d, off);
                best = fmaxf(best, d);
            }
        }
    }
    if (lane == 0) g_M[row] = best - qw / Uf;
}

// ---------------- kernel 6: top-60 per batch (u64 argmax) -----------------------
__global__ void topk_kernel() {
    int b = blockIdx.x;
    __shared__ float vals[QQ];
    __shared__ unsigned long long wred[8];
    int tid = threadIdx.x;
    for (int i = tid; i < QQ; i += 256) vals[i] = g_M[b * QQ + i];
    __syncthreads();
    for (int it = 0; it < UQ; it++) {
        unsigned long long best = 0ull;
        for (int i = tid; i < QQ; i += 256) {
            uint32_t u = __float_as_uint(vals[i]);
            u = (u & 0x80000000u) ? ~u : (u | 0x80000000u);
            unsigned long long cand =
                ((unsigned long long)u << 32) | (unsigned long long)(QQ - 1 - i);
            best = (cand > best) ? cand : best;
        }
#pragma unroll
        for (int off = 16; off > 0; off >>= 1) {
            unsigned long long o = __shfl_xor_sync(0xffffffffu, best, off);
            best = (o > best) ? o : best;
        }
        if ((tid & 31) == 0) wred[tid >> 5] = best;
        __syncthreads();
        if (tid == 0) {
            unsigned long long m = wred[0];
#pragma unroll
            for (int w = 1; w < 8; w++) m = (wred[w] > m) ? wred[w] : m;
            int i = QQ - 1 - (int)(m & 0xFFFFFFFFull);
            g_topidx[b * UQ + it] = i;
            vals[i] = -3.4e38f;
        }
        __syncthreads();
    }
}

// ---------------- kernel 7: fill output with v-mean ------------------------------
__global__ void fill_kernel(float* __restrict__ out) {
    size_t f = (size_t)blockIdx.x * 256 + threadIdx.x;
    int d4 = (int)(f & (DD / 4 - 1));
    size_t row = f >> 7;
    int b = (int)(row >> 11);
    float4 val = *(const float4*)(g_vmean + b * DD + d4 * 4);
    ((float4*)out)[f] = val;
}

// ---------------- kernel 8: logits S1 = q_bar @ k^T * scale ----------------------
__global__ void __launch_bounds__(256)
logits_kernel(const float* __restrict__ q, const float* __restrict__ k) {
    int b = blockIdx.y;
    int n0 = blockIdx.x * 128;
    __shared__ int   tix[UQ];
    __shared__ float qs2[16][64];
    __shared__ float ks2[16][128];
    int tid = threadIdx.x;
    if (tid < UQ) tix[tid] = g_topidx[b * UQ + tid];

    int tx = tid & 15, ty = tid >> 4;
    float acc[4][8];
#pragma unroll
    for (int i = 0; i < 4; i++)
#pragma unroll
        for (int j = 0; j < 8; j++) acc[i][j] = 0.f;

    const float* qb = q + (size_t)b * QQ * DD;
    const float* kb = k + (size_t)b * KVN * DD;

    for (int dt = 0; dt < DD; dt += 16) {
        __syncthreads();
        if (tid < 240) {
            int i = tid >> 2, hh = (tid & 3) * 4;
            float4 v4 = *(const float4*)(qb + (size_t)tix[i] * DD + dt + hh);
            qs2[hh + 0][i] = v4.x; qs2[hh + 1][i] = v4.y;
            qs2[hh + 2][i] = v4.z; qs2[hh + 3][i] = v4.w;
        }
        {
            int r2 = tid >> 1, h2 = (tid & 1) * 8;
            float4 a4 = *(const float4*)(kb + (size_t)(n0 + r2) * DD + dt + h2);
            float4 b4 = *(const float4*)(kb + (size_t)(n0 + r2) * DD + dt + h2 + 4);
            ks2[h2 + 0][r2] = a4.x; ks2[h2 + 1][r2] = a4.y;
            ks2[h2 + 2][r2] = a4.z; ks2[h2 + 3][r2] = a4.w;
            ks2[h2 + 4][r2] = b4.x; ks2[h2 + 5][r2] = b4.y;
            ks2[h2 + 6][r2] = b4.z; ks2[h2 + 7][r2] = b4.w;
        }
        __syncthreads();
#pragma unroll
        for (int kk = 0; kk < 16; kk++) {
            float a[4], bb[8];
            *(float4*)&a[0]  = *(float4*)&qs2[kk][ty * 4];
            *(float4*)&bb[0] = *(float4*)&ks2[kk][tx * 8];
            *(float4*)&bb[4] = *(float4*)&ks2[kk][tx * 8 + 4];
#pragma unroll
            for (int i = 0; i < 4; i++)
#pragma unroll
                for (int j = 0; j < 8; j++)
                    acc[i][j] += a[i] * bb[j];
        }
    }
    float scale = rsqrtf((float)KVN);
#pragma unroll
    for (int ii = 0; ii < 4; ii++) {
        int i = ty * 4 + ii;
        if (i < UQ) {
#pragma unroll
            for (int j = 0; j < 8; j++)
                g_S1[((size_t)b * UQ + i) * KVN + n0 + tx * 8 + j] =
                    acc[ii][j] * scale;
        }
    }
}

// ---------------- kernel 9: row softmax over S1 ----------------------------------
__global__ void softmax_kernel() {
    int row = blockIdx.x;
    float* p = g_S1 + (size_t)row * KVN;
    __shared__ float sred[256];
    int tid = threadIdx.x;

    float m = -3.4e38f;
    for (int i = tid; i < KVN; i += 256) m = fmaxf(m, p[i]);
    sred[tid] = m; __syncthreads();
    for (int s = 128; s > 0; s >>= 1) {
        if (tid < s) sred[tid] = fmaxf(sred[tid], sred[tid + s]);
        __syncthreads();
    }
    m = sred[0];
    __syncthreads();

    float sum = 0.f;
    for (int i = tid; i < KVN; i += 256) {
        float e = expf(p[i] - m);
        p[i] = e;
        sum += e;
    }
    sred[tid] = sum; __syncthreads();
    for (int s = 128; s > 0; s >>= 1) {
        if (tid < s) sred[tid] += sred[tid + s];
        __syncthreads();
    }
    float inv = 1.0f / sred[0];
    for (int i = tid; i < KVN; i += 256) p[i] *= inv;
}

// ---------------- kernel 10: O partials = P @ V (split kv) -----------------------
__global__ void __launch_bounds__(256)
pv_kernel(const float* __restrict__ v) {
    int b = blockIdx.z;
    int s = blockIdx.y;
    int d0 = blockIdx.x * 128;
    int kv0 = s * (KVN / PVS);

    __shared__ float ps[16][64];
    __shared__ float vs[16][128];
    int tid = threadIdx.x;
    int tx = tid & 15, ty = tid >> 4;
    float acc[4][8];
#pragma unroll
    for (int i = 0; i < 4; i++)
#pragma unroll
        for (int j = 0; j < 8; j++) acc[i][j] = 0.f;

    const float* vb = v + (size_t)b * KVN * DD;

    for (int kt = 0; kt < KVN / PVS; kt += 16) {
        __syncthreads();
        if (tid < 240) {
            int i = tid >> 2, hh = (tid & 3) * 4;
            float4 a4 = *(const float4*)(g_S1 + ((size_t)b * UQ + i) * KVN
                                         + kv0 + kt + hh);
            ps[hh + 0][i] = a4.x; ps[hh + 1][i] = a4.y;
            ps[hh + 2][i] = a4.z; ps[hh + 3][i] = a4.w;
        }
        {
            int kkr = tid >> 4, dc = (tid & 15) * 8;
            float4 a4 = *(const float4*)(vb + (size_t)(kv0 + kt + kkr) * DD + d0 + dc);
            float4 b4 = *(const float4*)(vb + (size_t)(kv0 + kt + kkr) * DD + d0 + dc + 4);
            vs[kkr][dc + 0] = a4.x; vs[kkr][dc + 1] = a4.y;
            vs[kkr][dc + 2] = a4.z; vs[kkr][dc + 3] = a4.w;
            vs[kkr][dc + 4] = b4.x; vs[kkr][dc + 5] = b4.y;
            vs[kkr][dc + 6] = b4.z; vs[kkr][dc + 7] = b4.w;
        }
        __syncthreads();
#pragma unroll
        for (int kk = 0; kk < 16; kk++) {
            float a[4], bb[8];
            *(float4*)&a[0]  = *(float4*)&ps[kk][ty * 4];
            *(float4*)&bb[0] = *(float4*)&vs[kk][tx * 8];
            *(float4*)&bb[4] = *(float4*)&vs[kk][tx * 8 + 4];
#pragma unroll
            for (int i = 0; i < 4; i++)
#pragma unroll
                for (int j = 0; j < 8; j++)
                    acc[i][j] += a[i] * bb[j];
        }
    }
#pragma unroll
    for (int ii = 0; ii < 4; ii++) {
        int i = ty * 4 + ii;
        if (i < UQ) {
#pragma unroll
            for (int j = 0; j < 8; j++)
                g_Opart[(((size_t)s * BB + b) * UQ + i) * DD + d0 + tx * 8 + j] =
                    acc[ii][j];
        }
    }
}

// ---------------- kernel 11: reduce PV partials + scatter ------------------------
__global__ void oreduce_kernel(float* __restrict__ out) {
    int idx = blockIdx.x * 256 + threadIdx.x;
    if (idx >= BB * UQ * DD) return;
    int d = idx % DD;
    int rest = idx / DD;
    int i = rest % UQ;
    int b = rest / UQ;
    float s = 0.f;
#pragma unroll
    for (int p = 0; p < PVS; p++)
        s += g_Opart[(((size_t)p * BB + b) * UQ + i) * DD + d];
    int row = g_topidx[b * UQ + i];
    out[((size_t)b * QQ + row) * DD + d] = s;
}

// ---------------- launch ----------------------------------------------------------
extern "C" void kernel_launch(void* const* d_in, const int* in_sizes, int n_in,
                              void* d_out, int out_size) {
    const float* q    = (const float*)d_in[0];
    const float* k    = (const float*)d_in[1];
    const float* v    = (const float*)d_in[2];
    const int*   sidx = (const int*)d_in[3];
    float* out = (float*)d_out;
    int U = in_sizes[3] / BB;

    split_kernel<<<(BB * QQ * DD / 4) / 256, 256>>>(q, k);
    zero_count_kernel<<<(BB * KVN + 255) / 256, 256>>>();
    count_kernel<<<(BB * U + 255) / 256, 256>>>(sidx, U);
    wsum_part_kernel<<<dim3(DD / 128, WS_SPLIT, BB), 128>>>(k, v);
    wsum_reduce_kernel<<<(BB * DD + 255) / 256, 256>>>();
    qkmax_tc_kernel<<<dim3(QQ / 128, KVN / 128, BB), 256>>>();
    refine_kernel<<<(BB * QQ) / 8, 256>>>(q, k, (float)U);
    topk_kernel<<<BB, 256>>>();
    fill_kernel<<<(BB * QQ * DD / 4) / 256, 256>>>(out);
    logits_kernel<<<dim3(KVN / 128, BB), 256>>>(q, k);
    softmax_kernel<<<BB * UQ, 256>>>();
    pv_kernel<<<dim3(DD / 128, PVS, BB), 256>>>(v);
    oreduce_kernel<<<(BB * UQ * DD + 255) / 256, 256>>>(out);
}

// round 6
// speedup vs baseline: 2.7855x; 1.0940x over previous
#include <cuda_runtime.h>
#include <cuda_bf16.h>
#include <math.h>
#include <stdint.h>

// Problem constants
#define BB    4
#define QQ    2048
#define KVN   2048
#define DD    512
#define UQ    60
#define NTILES (KVN / 128)       // 16
#define WS_SPLIT 32
#define KVC   (KVN / WS_SPLIT)   // 64
#define PVS   32
#define CHUNK 32
#define NSTAGE (DD / CHUNK)      // 16
#define WWIN  1.0f               // rescue window (6-sigma bf16 dot error ~0.4)

// ---------------- scratch ----------------------------------------------------
__device__ int   g_count[BB * KVN];
__device__ float g_wspart[WS_SPLIT * BB * DD];
__device__ float g_vmpart[WS_SPLIT * BB * DD];
__device__ float g_wsum[BB * DD];
__device__ float g_vmean[BB * DD];
__device__ float g_M[BB * QQ];
__device__ float g_Mpart[BB * QQ * NTILES];
__device__ uint32_t g_cand[(size_t)BB * QQ * NTILES * 4];   // 128-bit masks
__device__ int   g_topidx[BB * UQ];
__device__ float g_S1[(size_t)BB * UQ * KVN];
__device__ float g_Opart[(size_t)PVS * BB * UQ * DD];
__device__ __nv_bfloat16 g_qhi[(size_t)BB * QQ * DD];
__device__ __nv_bfloat16 g_khi[(size_t)BB * KVN * DD];

// ---------------- PTX helpers -------------------------------------------------
__device__ __forceinline__ uint32_t smem_u32(const void* p) {
    return (uint32_t)__cvta_generic_to_shared(p);
}
__device__ __forceinline__ void cpa16(uint32_t saddr, const void* g) {
    asm volatile("cp.async.cg.shared.global [%0], [%1], 16;" :: "r"(saddr), "l"(g));
}
__device__ __forceinline__ void ldsm4(uint32_t& r0, uint32_t& r1, uint32_t& r2,
                                      uint32_t& r3, uint32_t addr) {
    asm volatile("ldmatrix.sync.aligned.m8n8.x4.shared.b16 {%0,%1,%2,%3}, [%4];"
                 : "=r"(r0), "=r"(r1), "=r"(r2), "=r"(r3) : "r"(addr));
}
__device__ __forceinline__ void mma16816(float* c, const uint32_t* a,
                                         uint32_t b0, uint32_t b1) {
    asm volatile(
        "mma.sync.aligned.m16n8k16.row.col.f32.bf16.bf16.f32 "
        "{%0,%1,%2,%3}, {%4,%5,%6,%7}, {%8,%9}, {%0,%1,%2,%3};"
        : "+f"(c[0]), "+f"(c[1]), "+f"(c[2]), "+f"(c[3])
        : "r"(a[0]), "r"(a[1]), "r"(a[2]), "r"(a[3]), "r"(b0), "r"(b1));
}

// ---------------- kernel 0: bf16 hi of q and k ---------------------------------
__global__ void split_kernel(const float* __restrict__ q, const float* __restrict__ k) {
    size_t i = (size_t)blockIdx.x * 256 + threadIdx.x;   // float4 index
    float4 a = ((const float4*)q)[i];
    __nv_bfloat162 h01, h23;
    h01.x = __float2bfloat16(a.x); h01.y = __float2bfloat16(a.y);
    h23.x = __float2bfloat16(a.z); h23.y = __float2bfloat16(a.w);
    ((__nv_bfloat162*)g_qhi)[i * 2] = h01; ((__nv_bfloat162*)g_qhi)[i * 2 + 1] = h23;

    float4 bvec = ((const float4*)k)[i];
    h01.x = __float2bfloat16(bvec.x); h01.y = __float2bfloat16(bvec.y);
    h23.x = __float2bfloat16(bvec.z); h23.y = __float2bfloat16(bvec.w);
    ((__nv_bfloat162*)g_khi)[i * 2] = h01; ((__nv_bfloat162*)g_khi)[i * 2 + 1] = h23;
}

// ---------------- kernels 1,2: counts -----------------------------------------
__global__ void zero_count_kernel() {
    int i = blockIdx.x * blockDim.x + threadIdx.x;
    if (i < BB * KVN) g_count[i] = 0;
}
__global__ void count_kernel(const int* __restrict__ sidx, int U) {
    int i = blockIdx.x * blockDim.x + threadIdx.x;
    if (i < BB * U) {
        int b = i / U;
        atomicAdd(&g_count[b * KVN + sidx[i]], 1);
    }
}

// ---------------- kernel 3: weighted key sum + v mean --------------------------
__global__ void wsum_part_kernel(const float* __restrict__ k,
                                 const float* __restrict__ v) {
    int b = blockIdx.z;
    int s = blockIdx.y;
    int d = blockIdx.x * 128 + threadIdx.x;

    __shared__ float cntf[KVC];
    if (threadIdx.x < KVC)
        cntf[threadIdx.x] = (float)g_count[b * KVN + s * KVC + threadIdx.x];
    __syncthreads();

    const float* kp = k + ((size_t)b * KVN + (size_t)s * KVC) * DD + d;
    const float* vp = v + ((size_t)b * KVN + (size_t)s * KVC) * DD + d;
    float ws = 0.f, vm = 0.f;
#pragma unroll 8
    for (int j = 0; j < KVC; j++) {
        ws += cntf[j] * kp[(size_t)j * DD];
        vm += vp[(size_t)j * DD];
    }
    g_wspart[((size_t)s * BB + b) * DD + d] = ws;
    g_vmpart[((size_t)s * BB + b) * DD + d] = vm;
}

__global__ void wsum_reduce_kernel() {
    int idx = blockIdx.x * blockDim.x + threadIdx.x;
    if (idx >= BB * DD) return;
    int b = idx / DD, d = idx % DD;
    float ws = 0.f, vm = 0.f;
#pragma unroll
    for (int s = 0; s < WS_SPLIT; s++) {
        ws += g_wspart[((size_t)s * BB + b) * DD + d];
        vm += g_vmpart[((size_t)s * BB + b) * DD + d];
    }
    g_wsum[idx] = ws;
    g_vmean[idx] = vm * (1.0f / KVN);
}

// ---------------- kernel 4: approx QK^T (bf16 HMMA) -> rowmax + cand bits ------
// grid (16,16,4), block 256 (8 warps: 2m x 4n), warp tile 64x32, K-step 32,
// 3-stage cp.async pipeline, ONE __syncthreads per chunk.
__global__ void __launch_bounds__(256, 2)
qkmax_tc_kernel() {
    __shared__ __nv_bfloat16 sA[3][128][40];
    __shared__ __nv_bfloat16 sB[3][128][40];
    __shared__ int      cmask[128];
    __shared__ float    smax[128][4];
    __shared__ float    rmax[128];
    __shared__ uint32_t bits[128][4];

    const int tid = threadIdx.x, lane = tid & 31, warp = tid >> 5;
    const int wm = warp >> 2, wn = warp & 3;
    const int b = blockIdx.z;
    const int m0 = blockIdx.x * 128, n0 = blockIdx.y * 128;

    const __nv_bfloat16* qh = g_qhi + (size_t)b * QQ * DD;
    const __nv_bfloat16* kh = g_khi + (size_t)b * KVN * DD;

    if (tid < 128) {
        cmask[tid] = g_count[b * KVN + n0 + tid];
        bits[tid][0] = 0u; bits[tid][1] = 0u; bits[tid][2] = 0u; bits[tid][3] = 0u;
    }

    const int lrow = tid >> 1, lhalf = tid & 1;
    const size_t gaoff = (size_t)(m0 + lrow) * DD + lhalf * 8;
    const size_t gboff = (size_t)(n0 + lrow) * DD + lhalf * 8;
    const uint32_t saA = smem_u32(&sA[0][lrow][lhalf * 8]);
    const uint32_t saB = smem_u32(&sB[0][lrow][lhalf * 8]);
    const uint32_t BUFSTRIDE = 128 * 40 * 2;   // 10240 bytes

    const int lr = lane & 15;
    const int lc8 = (lane >> 4) * 8;
    const uint32_t aAh = smem_u32(&sA[0][wm * 64 + lr][lc8]);
    const uint32_t aBh = smem_u32(&sB[0][wn * 32 + lr][lc8]);

    float acc[4][4][4];
#pragma unroll
    for (int mt = 0; mt < 4; mt++)
#pragma unroll
        for (int nt = 0; nt < 4; nt++)
#pragma unroll
            for (int r = 0; r < 4; r++) acc[mt][nt][r] = 0.f;

    auto issue = [&](int ks) {
        uint32_t bo = (uint32_t)(ks % 3) * BUFSTRIDE;
        int dt = ks * CHUNK;
        cpa16(saA + bo,      qh + gaoff + dt);
        cpa16(saA + bo + 32, qh + gaoff + dt + 16);
        cpa16(saB + bo,      kh + gboff + dt);
        cpa16(saB + bo + 32, kh + gboff + dt + 16);
        asm volatile("cp.async.commit_group;");
    };

    issue(0);
    issue(1);
#pragma unroll 1
    for (int ks = 0; ks < NSTAGE; ks++) {
        if (ks < NSTAGE - 1)
            asm volatile("cp.async.wait_group 1;");
        else
            asm volatile("cp.async.wait_group 0;");
        __syncthreads();
        // safe: every warp's compute(ks-1) on buffer (ks+2)%3 precedes this barrier
        if (ks + 2 < NSTAGE) issue(ks + 2);

        uint32_t bo = (uint32_t)(ks % 3) * BUFSTRIDE;
#pragma unroll
        for (int kh2 = 0; kh2 < 2; kh2++) {
            uint32_t ko = bo + kh2 * 32;
            uint32_t a[4][4], bf[2][4];
#pragma unroll
            for (int mt = 0; mt < 4; mt++)
                ldsm4(a[mt][0], a[mt][1], a[mt][2], a[mt][3], aAh + ko + mt * 1280);
#pragma unroll
            for (int nc = 0; nc < 2; nc++)
                ldsm4(bf[nc][0], bf[nc][1], bf[nc][2], bf[nc][3], aBh + ko + nc * 1280);
#pragma unroll
            for (int mt = 0; mt < 4; mt++)
#pragma unroll
                for (int nt = 0; nt < 4; nt++) {
                    int nc = nt >> 1, s = nt & 1;
                    mma16816(acc[mt][nt], a[mt], bf[nc][s], bf[nc][2 + s]);
                }
        }
    }

    // ---- epilogue: masked row-max + candidate bitmask ----
#pragma unroll
    for (int nt = 0; nt < 4; nt++) {
        int c = wn * 32 + nt * 8 + (lane & 3) * 2;
        bool ok0 = cmask[c] > 0, ok1 = cmask[c + 1] > 0;
#pragma unroll
        for (int mt = 0; mt < 4; mt++) {
            if (!ok0) { acc[mt][nt][0] = -3.0e38f; acc[mt][nt][2] = -3.0e38f; }
            if (!ok1) { acc[mt][nt][1] = -3.0e38f; acc[mt][nt][3] = -3.0e38f; }
        }
    }
    float rm[8];
#pragma unroll
    for (int i = 0; i < 8; i++) rm[i] = -3.0e38f;
#pragma unroll
    for (int nt = 0; nt < 4; nt++)
#pragma unroll
        for (int mt = 0; mt < 4; mt++) {
            rm[mt * 2]     = fmaxf(rm[mt * 2],     fmaxf(acc[mt][nt][0], acc[mt][nt][1]));
            rm[mt * 2 + 1] = fmaxf(rm[mt * 2 + 1], fmaxf(acc[mt][nt][2], acc[mt][nt][3]));
        }
#pragma unroll
    for (int i = 0; i < 8; i++) {
        rm[i] = fmaxf(rm[i], __shfl_xor_sync(0xffffffffu, rm[i], 1));
        rm[i] = fmaxf(rm[i], __shfl_xor_sync(0xffffffffu, rm[i], 2));
    }
    if ((lane & 3) == 0) {
        int g = lane >> 2;
#pragma unroll
        for (int mt = 0; mt < 4; mt++) {
            smax[wm * 64 + mt * 16 + g][wn]     = rm[mt * 2];
            smax[wm * 64 + mt * 16 + g + 8][wn] = rm[mt * 2 + 1];
        }
    }
    __syncthreads();
    if (tid < 128)
        rmax[tid] = fmaxf(fmaxf(smax[tid][0], smax[tid][1]),
                          fmaxf(smax[tid][2], smax[tid][3]));
    __syncthreads();

    {
        int g = lane >> 2;
#pragma unroll
        for (int mt = 0; mt < 4; mt++) {
            int r0 = wm * 64 + mt * 16 + g;
            float t0 = rmax[r0] - WWIN, t1 = rmax[r0 + 8] - WWIN;
#pragma unroll
            for (int nt = 0; nt < 4; nt++) {
                int c = wn * 32 + nt * 8 + (lane & 3) * 2;
                if (acc[mt][nt][0] >= t0) atomicOr(&bits[r0][c >> 5], 1u << (c & 31));
                if (acc[mt][nt][1] >= t0) atomicOr(&bits[r0][(c + 1) >> 5], 1u << ((c + 1) & 31));
                if (acc[mt][nt][2] >= t1) atomicOr(&bits[r0 + 8][c >> 5], 1u << (c & 31));
                if (acc[mt][nt][3] >= t1) atomicOr(&bits[r0 + 8][(c + 1) >> 5], 1u << ((c + 1) & 31));
            }
        }
    }
    __syncthreads();
    if (tid < 128) {
        size_t ro = ((size_t)b * QQ + m0 + tid) * NTILES + blockIdx.y;
        g_Mpart[ro] = rmax[tid];
        *(uint4*)&g_cand[ro * 4] = *(uint4*)&bits[tid][0];
    }
}

// ---------------- kernel 5: refine — exact max + M -----------------------------
__global__ void refine_kernel(const float* __restrict__ q,
                              const float* __restrict__ k, float Uf) {
    int row = blockIdx.x * 8 + (threadIdx.x >> 5);   // b*QQ + qi
    int lane = threadIdx.x & 31;
    if (row >= BB * QQ) return;
    int b = row / QQ;

    const float* mp = g_Mpart + (size_t)row * NTILES;
    float gmax = -3.0e38f;
#pragma unroll
    for (int t = 0; t < NTILES; t++) gmax = fmaxf(gmax, mp[t]);
    float thr = gmax - WWIN;

    const float* qr = q + (size_t)row * DD;
    const float* ws = g_wsum + b * DD;
    float qw = 0.f;
#pragma unroll
    for (int t = 0; t < DD / 32; t++)
        qw += qr[t * 32 + lane] * ws[t * 32 + lane];
#pragma unroll
    for (int off = 16; off > 0; off >>= 1)
        qw += __shfl_xor_sync(0xffffffffu, qw, off);

    const float* kb = k + (size_t)b * KVN * DD;
    float best = -3.0e38f;
#pragma unroll 1
    for (int t = 0; t < NTILES; t++) {
        if (mp[t] < thr) continue;
        const uint32_t* cw = g_cand + ((size_t)row * NTILES + t) * 4;
#pragma unroll
        for (int w = 0; w < 4; w++) {
            uint32_t m = cw[w];
            while (m) {
                int bit = __ffs(m) - 1;
                m &= m - 1;
                int col = t * 128 + w * 32 + bit;
                const float* kr = kb + (size_t)col * DD;
                float d = 0.f;
#pragma unroll
                for (int tt = 0; tt < DD / 32; tt++)
                    d += qr[tt * 32 + lane] * kr[tt * 32 + lane];
#pragma unroll
                for (int off = 16; off > 0; off >>= 1)
                    d += __shfl_xor_sync(0xffffffffu, d, off);
                best = fmaxf(best, d);
            }
        }
    }
    if (lane == 0) g_M[row] = best - qw / Uf;
}

// ---------------- kernel 6: top-60 per batch (u64 argmax) -----------------------
__global__ void topk_kernel() {
    int b = blockIdx.x;
    __shared__ float vals[QQ];
    __shared__ unsigned long long wred[8];
    int tid = threadIdx.x;
    for (int i = tid; i < QQ; i += 256) vals[i] = g_M[b * QQ + i];
    __syncthreads();
    for (int it = 0; it < UQ; it++) {
        unsigned long long best = 0ull;
        for (int i = tid; i < QQ; i += 256) {
            uint32_t u = __float_as_uint(vals[i]);
            u = (u & 0x80000000u) ? ~u : (u | 0x80000000u);
            unsigned long long cand =
                ((unsigned long long)u << 32) | (unsigned long long)(QQ - 1 - i);
            best = (cand > best) ? cand : best;
        }
#pragma unroll
        for (int off = 16; off > 0; off >>= 1) {
            unsigned long long o = __shfl_xor_sync(0xffffffffu, best, off);
            best = (o > best) ? o : best;
        }
        if ((tid & 31) == 0) wred[tid >> 5] = best;
        __syncthreads();
        if (tid == 0) {
            unsigned long long m = wred[0];
#pragma unroll
            for (int w = 1; w < 8; w++) m = (wred[w] > m) ? wred[w] : m;
            int i = QQ - 1 - (int)(m & 0xFFFFFFFFull);
            g_topidx[b * UQ + it] = i;
            vals[i] = -3.4e38f;
        }
        __syncthreads();
    }
}

// ---------------- kernel 7: fill output with v-mean ------------------------------
__global__ void fill_kernel(float* __restrict__ out) {
    size_t f = (size_t)blockIdx.x * 256 + threadIdx.x;
    int d4 = (int)(f & (DD / 4 - 1));
    size_t row = f >> 7;
    int b = (int)(row >> 11);
    float4 val = *(const float4*)(g_vmean + b * DD + d4 * 4);
    ((float4*)out)[f] = val;
}

// ---------------- kernel 8: logits S1 = q_bar @ k^T * scale ----------------------
// grid (KVN/64, BB), block 256; thread microtile 4q x 4kv, d-step 16
__global__ void __launch_bounds__(256)
logits_kernel(const float* __restrict__ q, const float* __restrict__ k) {
    int b = blockIdx.y;
    int n0 = blockIdx.x * 64;
    __shared__ int   tix[UQ];
    __shared__ float qs2[16][64];
    __shared__ float ks2[16][64];
    int tid = threadIdx.x;
    if (tid < UQ) tix[tid] = g_topidx[b * UQ + tid];

    int tx = tid & 15, ty = tid >> 4;
    float acc[4][4];
#pragma unroll
    for (int i = 0; i < 4; i++)
#pragma unroll
        for (int j = 0; j < 4; j++) acc[i][j] = 0.f;

    const float* qb = q + (size_t)b * QQ * DD;
    const float* kb = k + (size_t)b * KVN * DD;

    for (int dt = 0; dt < DD; dt += 16) {
        __syncthreads();
        if (tid < 240) {
            int i = tid >> 2, hh = (tid & 3) * 4;
            float4 v4 = *(const float4*)(qb + (size_t)tix[i] * DD + dt + hh);
            qs2[hh + 0][i] = v4.x; qs2[hh + 1][i] = v4.y;
            qs2[hh + 2][i] = v4.z; qs2[hh + 3][i] = v4.w;
        }
        {
            int r2 = tid >> 2, h2 = (tid & 3) * 4;
            float4 a4 = *(const float4*)(kb + (size_t)(n0 + r2) * DD + dt + h2);
            ks2[h2 + 0][r2] = a4.x; ks2[h2 + 1][r2] = a4.y;
            ks2[h2 + 2][r2] = a4.z; ks2[h2 + 3][r2] = a4.w;
        }
        __syncthreads();
#pragma unroll
        for (int kk = 0; kk < 16; kk++) {
            float a[4], bb[4];
            *(float4*)&a[0]  = *(float4*)&qs2[kk][ty * 4];
            *(float4*)&bb[0] = *(float4*)&ks2[kk][tx * 4];
#pragma unroll
            for (int i = 0; i < 4; i++)
#pragma unroll
                for (int j = 0; j < 4; j++)
                    acc[i][j] += a[i] * bb[j];
        }
    }
    float scale = rsqrtf((float)KVN);
#pragma unroll
    for (int ii = 0; ii < 4; ii++) {
        int i = ty * 4 + ii;
        if (i < UQ) {
#pragma unroll
            for (int j = 0; j < 4; j++)
                g_S1[((size_t)b * UQ + i) * KVN + n0 + tx * 4 + j] =
                    acc[ii][j] * scale;
        }
    }
}

// ---------------- kernel 9: row softmax over S1 ----------------------------------
__global__ void softmax_kernel() {
    int row = blockIdx.x;
    float* p = g_S1 + (size_t)row * KVN;
    __shared__ float sred[256];
    int tid = threadIdx.x;

    float m = -3.4e38f;
    for (int i = tid; i < KVN; i += 256) m = fmaxf(m, p[i]);
    sred[tid] = m; __syncthreads();
    for (int s = 128; s > 0; s >>= 1) {
        if (tid < s) sred[tid] = fmaxf(sred[tid], sred[tid + s]);
        __syncthreads();
    }
    m = sred[0];
    __syncthreads();

    float sum = 0.f;
    for (int i = tid; i < KVN; i += 256) {
        float e = expf(p[i] - m);
        p[i] = e;
        sum += e;
    }
    sred[tid] = sum; __syncthreads();
    for (int s = 128; s > 0; s >>= 1) {
        if (tid < s) sred[tid] += sred[tid + s];
        __syncthreads();
    }
    float inv = 1.0f / sred[0];
    for (int i = tid; i < KVN; i += 256) p[i] *= inv;
}

// ---------------- kernel 10: O partials = P @ V (split kv) -----------------------
// grid (DD/128, PVS, BB), block 256; microtile 4q x 8d, kv-step 16
__global__ void __launch_bounds__(256)
pv_kernel(const float* __restrict__ v) {
    int b = blockIdx.z;
    int s = blockIdx.y;
    int d0 = blockIdx.x * 128;
    int kv0 = s * (KVN / PVS);     // 64

    __shared__ float ps[16][64];
    __shared__ float vs[16][128];
    int tid = threadIdx.x;
    int tx = tid & 15, ty = tid >> 4;
    float acc[4][8];
#pragma unroll
    for (int i = 0; i < 4; i++)
#pragma unroll
        for (int j = 0; j < 8; j++) acc[i][j] = 0.f;

    const float* vb = v + (size_t)b * KVN * DD;

    for (int kt = 0; kt < KVN / PVS; kt += 16) {
        __syncthreads();
        if (tid < 240) {
            int i = tid >> 2, hh = (tid & 3) * 4;
            float4 a4 = *(const float4*)(g_S1 + ((size_t)b * UQ + i) * KVN
                                         + kv0 + kt + hh);
            ps[hh + 0][i] = a4.x; ps[hh + 1][i] = a4.y;
            ps[hh + 2][i] = a4.z; ps[hh + 3][i] = a4.w;
        }
        {
            int kkr = tid >> 4, dc = (tid & 15) * 8;
            float4 a4 = *(const float4*)(vb + (size_t)(kv0 + kt + kkr) * DD + d0 + dc);
            float4 b4 = *(const float4*)(vb + (size_t)(kv0 + kt + kkr) * DD + d0 + dc + 4);
            vs[kkr][dc + 0] = a4.x; vs[kkr][dc + 1] = a4.y;
            vs[kkr][dc + 2] = a4.z; vs[kkr][dc + 3] = a4.w;
            vs[kkr][dc + 4] = b4.x; vs[kkr][dc + 5] = b4.y;
            vs[kkr][dc + 6] = b4.z; vs[kkr][dc + 7] = b4.w;
        }
        __syncthreads();
#pragma unroll
        for (int kk = 0; kk < 16; kk++) {
            float a[4], bb[8];
            *(float4*)&a[0]  = *(float4*)&ps[kk][ty * 4];
            *(float4*)&bb[0] = *(float4*)&vs[kk][tx * 8];
            *(float4*)&bb[4] = *(float4*)&vs[kk][tx * 8 + 4];
#pragma unroll
            for (int i = 0; i < 4; i++)
#pragma unroll
                for (int j = 0; j < 8; j++)
                    acc[i][j] += a[i] * bb[j];
        }
    }
#pragma unroll
    for (int ii = 0; ii < 4; ii++) {
        int i = ty * 4 + ii;
        if (i < UQ) {
#pragma unroll
            for (int j = 0; j < 8; j++)
                g_Opart[(((size_t)s * BB + b) * UQ + i) * DD + d0 + tx * 8 + j] =
                    acc[ii][j];
        }
    }
}

// ---------------- kernel 11: reduce PV partials + scatter ------------------------
__global__ void oreduce_kernel(float* __restrict__ out) {
    int idx = blockIdx.x * 256 + threadIdx.x;
    if (idx >= BB * UQ * DD) return;
    int d = idx % DD;
    int rest = idx / DD;
    int i = rest % UQ;
    int b = rest / UQ;
    float s = 0.f;
#pragma unroll
    for (int p = 0; p < PVS; p++)
        s += g_Opart[(((size_t)p * BB + b) * UQ + i) * DD + d];
    int row = g_topidx[b * UQ + i];
    out[((size_t)b * QQ + row) * DD + d] = s;
}

// ---------------- launch ----------------------------------------------------------
extern "C" void kernel_launch(void* const* d_in, const int* in_sizes, int n_in,
                              void* d_out, int out_size) {
    const float* q    = (const float*)d_in[0];
    const float* k    = (const float*)d_in[1];
    const float* v    = (const float*)d_in[2];
    const int*   sidx = (const int*)d_in[3];
    float* out = (float*)d_out;
    int U = in_sizes[3] / BB;

    split_kernel<<<(BB * QQ * DD / 4) / 256, 256>>>(q, k);
    zero_count_kernel<<<(BB * KVN + 255) / 256, 256>>>();
    count_kernel<<<(BB * U + 255) / 256, 256>>>(sidx, U);
    wsum_part_kernel<<<dim3(DD / 128, WS_SPLIT, BB), 128>>>(k, v);
    wsum_reduce_kernel<<<(BB * DD + 255) / 256, 256>>>();
    qkmax_tc_kernel<<<dim3(QQ / 128, KVN / 128, BB), 256>>>();
    refine_kernel<<<(BB * QQ) / 8, 256>>>(q, k, (float)U);
    topk_kernel<<<BB, 256>>>();
    fill_kernel<<<(BB * QQ * DD / 4) / 256, 256>>>(out);
    logits_kernel<<<dim3(KVN / 64, BB), 256>>>(q, k);
    softmax_kernel<<<BB * UQ, 256>>>();
    pv_kernel<<<dim3(DD / 128, PVS, BB), 256>>>(v);
    oreduce_kernel<<<(BB * UQ * DD + 255) / 256, 256>>>(out);
}